// round 3
// baseline (speedup 1.0000x reference)
#include <cuda_runtime.h>
#include <cstdint>
#include <cstddef>

#define NN   50000
#define INCH 512
#define H1D  400
#define H2D  800

// Scratch (device globals — no allocation allowed in kernel_launch)
__device__ float g_H1  [(size_t)NN * H1D];   // x @ W1
__device__ float g_out1[(size_t)NN * H1D];   // aggregated layer-1 output
__device__ float g_r1  [(size_t)NN * H1D];   // relu(out1 + b1)
__device__ float g_agg2[(size_t)NN * H1D];   // aggregated relu (pre-GEMM2)
__device__ float g_dinv[NN];
__device__ int   g_deg [NN];
__device__ int   g_is64;                     // edge_index dtype flag

// ---------------------------------------------------------------------------
// Edge-index dtype probe: int64 payloads (<50000) have all-zero odd words.
// ---------------------------------------------------------------------------
__global__ void k_detect(const int* __restrict__ w, int nwords) {
    if (threadIdx.x == 0 && blockIdx.x == 0) {
        int lim = nwords < 4096 ? nwords : 4096;
        int is64 = 1;
        for (int i = 1; i < lim; i += 2)
            if (w[i] != 0) { is64 = 0; break; }
        g_is64 = is64;
    }
}

__device__ __forceinline__ int edge_at(const void* ei, long long idx) {
    if (g_is64) return (int)((const long long*)ei)[idx];
    return ((const int*)ei)[idx];
}

// ---------------------------------------------------------------------------
// Degree / normalization
// ---------------------------------------------------------------------------
__global__ void k_zero_deg() {
    int i = blockIdx.x * blockDim.x + threadIdx.x;
    if (i < NN) g_deg[i] = 0;
}

__global__ void k_count(const void* __restrict__ ei, int E) {
    int e = blockIdx.x * blockDim.x + threadIdx.x;
    if (e >= E) return;
    int d = edge_at(ei, (long long)E + e);   // dst row
    if ((unsigned)d < NN) atomicAdd(&g_deg[d], 1);
}

__global__ void k_dinv() {
    int i = blockIdx.x * blockDim.x + threadIdx.x;
    if (i < NN) g_dinv[i] = rsqrtf((float)g_deg[i] + 1.0f);  // +1 self-loop
}

// ---------------------------------------------------------------------------
// Tiled fp32 GEMM: C[M,N] = A[M,K] @ B[K,N]
// EPI==0: write C = acc AND C2 = acc * dinv[row]^2 (self-loop init for layer 1)
// EPI==1: write C = acc + bias[col]                 (final output)
// Requires K % 16 == 0, N % 4 == 0.
// ---------------------------------------------------------------------------
template<int EPI>
__global__ __launch_bounds__(256)
void k_sgemm(const float* __restrict__ A, const float* __restrict__ B,
             float* __restrict__ C, float* __restrict__ C2,
             const float* __restrict__ bias, int M, int N, int K)
{
    const int BM = 128, BN = 64, BK = 16;
    __shared__ float As[BK][BM];
    __shared__ float Bs[BK][BN];

    int tid = threadIdx.x;
    int bm = blockIdx.y * BM;
    int bn = blockIdx.x * BN;
    int tr = (tid >> 4) * 8;   // row offset in tile: 0..120
    int tc = (tid & 15) * 4;   // col offset in tile: 0..60

    float acc[8][4];
#pragma unroll
    for (int i = 0; i < 8; i++)
#pragma unroll
        for (int j = 0; j < 4; j++) acc[i][j] = 0.f;

    for (int k0 = 0; k0 < K; k0 += BK) {
        // A tile: 128x16 = 512 float4 (transposed into As[k][m])
#pragma unroll
        for (int t = 0; t < 2; t++) {
            int q   = tid + t * 256;
            int row = q >> 2;
            int kq  = (q & 3) * 4;
            float4 v = make_float4(0.f, 0.f, 0.f, 0.f);
            int gr = bm + row;
            if (gr < M) v = *(const float4*)(A + (size_t)gr * K + k0 + kq);
            As[kq + 0][row] = v.x;
            As[kq + 1][row] = v.y;
            As[kq + 2][row] = v.z;
            As[kq + 3][row] = v.w;
        }
        // B tile: 16x64 = 256 float4
        {
            int row = tid >> 4;
            int nq  = (tid & 15) * 4;
            float4 v = make_float4(0.f, 0.f, 0.f, 0.f);
            int gc = bn + nq;
            if (gc + 3 < N) v = *(const float4*)(B + (size_t)(k0 + row) * N + gc);
            *(float4*)&Bs[row][nq] = v;
        }
        __syncthreads();

#pragma unroll
        for (int kk = 0; kk < BK; kk++) {
            float a[8], b[4];
#pragma unroll
            for (int i = 0; i < 8; i++) a[i] = As[kk][tr + i];
#pragma unroll
            for (int j = 0; j < 4; j++) b[j] = Bs[kk][tc + j];
#pragma unroll
            for (int i = 0; i < 8; i++)
#pragma unroll
                for (int j = 0; j < 4; j++) acc[i][j] += a[i] * b[j];
        }
        __syncthreads();
    }

#pragma unroll
    for (int i = 0; i < 8; i++) {
        int r = bm + tr + i;
        if (r >= M) continue;
        float scale = 0.f;
        if (EPI == 0) { float d = g_dinv[r]; scale = d * d; }
#pragma unroll
        for (int j = 0; j < 4; j++) {
            int c = bn + tc + j;
            if (c >= N) continue;
            float v = acc[i][j];
            if (EPI == 0) {
                C [(size_t)r * N + c] = v;
                C2[(size_t)r * N + c] = v * scale;
            } else {
                C [(size_t)r * N + c] = v + bias[c];
            }
        }
    }
}

// ---------------------------------------------------------------------------
// relu(out1 + b1) -> r1, and init agg2 = r1 * dinv^2 (self-loop of layer 2)
// ---------------------------------------------------------------------------
__global__ void k_relu_agg2init(const float* __restrict__ b1) {
    const int TOT4 = NN * (H1D / 4);
    int i4 = blockIdx.x * blockDim.x + threadIdx.x;
    if (i4 >= TOT4) return;
    int node = i4 / (H1D / 4);
    int f4   = i4 - node * (H1D / 4);
    float4 v  = *((const float4*)g_out1 + i4);
    float4 bb = *((const float4*)b1 + f4);
    v.x = fmaxf(v.x + bb.x, 0.f);
    v.y = fmaxf(v.y + bb.y, 0.f);
    v.z = fmaxf(v.z + bb.z, 0.f);
    v.w = fmaxf(v.w + bb.w, 0.f);
    *((float4*)g_r1 + i4) = v;
    float d = g_dinv[node];
    float s = d * d;
    float4 w = make_float4(v.x * s, v.y * s, v.z * s, v.w * s);
    *((float4*)g_agg2 + i4) = w;
}

// ---------------------------------------------------------------------------
// Edge scatter: one warp per edge. Out[dst] += Hin[src] * dinv[src]*dinv[dst]
// 400 floats/row = 100 float4 -> red.global.add.v4.f32 (sm_90+)
// ---------------------------------------------------------------------------
__global__ __launch_bounds__(256)
void k_scatter(const void* __restrict__ ei,
               const float* __restrict__ Hin,
               float* __restrict__ Out, int E)
{
    int g    = blockIdx.x * blockDim.x + threadIdx.x;
    int e    = g >> 5;
    int lane = g & 31;
    if (e >= E) return;
    int s = edge_at(ei, e);
    int d = edge_at(ei, (long long)E + e);
    if ((unsigned)s >= NN || (unsigned)d >= NN) return;
    float norm = g_dinv[s] * g_dinv[d];
    const float4* hp = (const float4*)(Hin + (size_t)s * H1D);
    float4*       op = (float4*)(Out + (size_t)d * H1D);
#pragma unroll 1
    for (int q = lane; q < H1D / 4; q += 32) {
        float4 v = hp[q];
        asm volatile("red.global.add.v4.f32 [%0], {%1, %2, %3, %4};"
                     :: "l"(op + q),
                        "f"(v.x * norm), "f"(v.y * norm),
                        "f"(v.z * norm), "f"(v.w * norm)
                     : "memory");
    }
}

// ---------------------------------------------------------------------------
extern "C" void kernel_launch(void* const* d_in, const int* in_sizes, int n_in,
                              void* d_out, int out_size)
{
    const float* x  = (const float*)d_in[0];
    const void*  ei = d_in[1];                  // int32 OR int64 — probed on device
    const float* W1 = (const float*)d_in[2];
    const float* b1 = (const float*)d_in[3];
    const float* W2 = (const float*)d_in[4];
    const float* b2 = (const float*)d_in[5];
    float* out = (float*)d_out;

    int E = in_sizes[1] / 2;   // element count of edge_index / 2, dtype-independent

    float *pH1, *pOut1, *pR1, *pAgg2;
    cudaGetSymbolAddress((void**)&pH1,   g_H1);
    cudaGetSymbolAddress((void**)&pOut1, g_out1);
    cudaGetSymbolAddress((void**)&pR1,   g_r1);
    cudaGetSymbolAddress((void**)&pAgg2, g_agg2);

    // 0) probe edge_index dtype (deterministic, data-dependent but stable)
    k_detect<<<1, 1>>>((const int*)ei, in_sizes[1]);

    // 1) degrees + normalization
    k_zero_deg<<<(NN + 255) / 256, 256>>>();
    k_count<<<(E + 255) / 256, 256>>>(ei, E);
    k_dinv<<<(NN + 255) / 256, 256>>>();

    // 2) H1 = x @ W1 ; out1 initialized with self-loop term H1*dinv^2
    dim3 g1((H1D + 63) / 64, (NN + 127) / 128);
    k_sgemm<0><<<g1, 256>>>(x, W1, pH1, pOut1, nullptr, NN, H1D, INCH);

    // 3) edge aggregation for layer 1
    int sblocks = (int)(((long long)E * 32 + 255) / 256);
    k_scatter<<<sblocks, 256>>>(ei, pH1, pOut1, E);

    // 4) relu + bias ; init agg2 with self-loop term
    k_relu_agg2init<<<(NN * (H1D / 4) + 255) / 256, 256>>>(b1);

    // 5) edge aggregation for layer 2 (on 400 features — BEFORE the GEMM,
    //    exploiting linearity: S(r1) @ W2 == S(r1 @ W2))
    k_scatter<<<sblocks, 256>>>(ei, pR1, pAgg2, E);

    // 6) out = agg2 @ W2 + b2
    dim3 g2((H2D + 63) / 64, (NN + 127) / 128);
    k_sgemm<1><<<g2, 256>>>(pAgg2, W2, out, nullptr, b2, NN, H2D, H1D);
}

// round 4
// speedup vs baseline: 1.0569x; 1.0569x over previous
#include <cuda_runtime.h>
#include <cstdint>
#include <cstddef>

#define NN   50000
#define INCH 512
#define H1D  400
#define H2D  800

// Scratch (device globals — no allocation allowed in kernel_launch)
__device__ float g_H1  [(size_t)NN * H1D];   // x @ W1
__device__ float g_out1[(size_t)NN * H1D];   // aggregated layer-1 output
__device__ float g_r1  [(size_t)NN * H1D];   // relu(out1 + b1)
__device__ float g_agg2[(size_t)NN * H1D];   // aggregated relu (pre-GEMM2)
__device__ float g_dinv[NN];
__device__ int   g_deg [NN];
__device__ int   g_is64;                     // edge_index dtype flag

// ---------------------------------------------------------------------------
// Edge-index dtype probe: int64 payloads (<50000) have all-zero odd words.
// ---------------------------------------------------------------------------
__global__ void k_detect(const int* __restrict__ w, int nwords) {
    if (threadIdx.x == 0 && blockIdx.x == 0) {
        int lim = nwords < 4096 ? nwords : 4096;
        int is64 = 1;
        for (int i = 1; i < lim; i += 2)
            if (w[i] != 0) { is64 = 0; break; }
        g_is64 = is64;
    }
}

__device__ __forceinline__ int edge_at(const void* ei, long long idx) {
    if (g_is64) return (int)((const long long*)ei)[idx];
    return ((const int*)ei)[idx];
}

// ---------------------------------------------------------------------------
// Degree / normalization
// ---------------------------------------------------------------------------
__global__ void k_zero_deg() {
    int i = blockIdx.x * blockDim.x + threadIdx.x;
    if (i < NN) g_deg[i] = 0;
}

__global__ void k_count(const void* __restrict__ ei, int E) {
    int e = blockIdx.x * blockDim.x + threadIdx.x;
    if (e >= E) return;
    int d = edge_at(ei, (long long)E + e);   // dst row
    if ((unsigned)d < NN) atomicAdd(&g_deg[d], 1);
}

__global__ void k_dinv() {
    int i = blockIdx.x * blockDim.x + threadIdx.x;
    if (i < NN) g_dinv[i] = rsqrtf((float)g_deg[i] + 1.0f);  // +1 self-loop
}

// ---------------------------------------------------------------------------
// Tiled fp32 GEMM with packed fma.rn.f32x2 (FFMA2, sm_103a):
// C[M,N] = A[M,K] @ B[K,N]
// Each thread computes 8 rows x 4 cols, rows paired into 64-bit f32x2 regs.
// EPI==0: write C = acc AND C2 = acc * dinv[row]^2 (self-loop init, layer 1)
// EPI==1: write C = acc + bias[col]                (final output)
// Requires K % 16 == 0, N % 4 == 0.
// ---------------------------------------------------------------------------
template<int EPI>
__global__ __launch_bounds__(256)
void k_sgemm(const float* __restrict__ A, const float* __restrict__ B,
             float* __restrict__ C, float* __restrict__ C2,
             const float* __restrict__ bias, int M, int N, int K)
{
    const int BM = 128, BN = 64, BK = 16;
    __shared__ __align__(16) float As[BK][BM];
    __shared__ __align__(16) float Bs[BK][BN];

    int tid = threadIdx.x;
    int bm = blockIdx.y * BM;
    int bn = blockIdx.x * BN;
    int tr = (tid >> 4) * 8;   // row offset in tile: 0..120 (multiple of 8)
    int tc = (tid & 15) * 4;   // col offset in tile: 0..60

    // acc2[ip][j] holds rows (tr+2ip, tr+2ip+1) x col (tc+j), packed f32x2
    unsigned long long acc2[4][4];
#pragma unroll
    for (int ip = 0; ip < 4; ip++)
#pragma unroll
        for (int j = 0; j < 4; j++) acc2[ip][j] = 0ull;  // (+0.f, +0.f)

    for (int k0 = 0; k0 < K; k0 += BK) {
        // A tile: 128x16 = 512 float4 (transposed into As[k][m])
#pragma unroll
        for (int t = 0; t < 2; t++) {
            int q   = tid + t * 256;
            int row = q >> 2;
            int kq  = (q & 3) * 4;
            float4 v = make_float4(0.f, 0.f, 0.f, 0.f);
            int gr = bm + row;
            if (gr < M) v = *(const float4*)(A + (size_t)gr * K + k0 + kq);
            As[kq + 0][row] = v.x;
            As[kq + 1][row] = v.y;
            As[kq + 2][row] = v.z;
            As[kq + 3][row] = v.w;
        }
        // B tile: 16x64 = 256 float4
        {
            int row = tid >> 4;
            int nq  = (tid & 15) * 4;
            float4 v = make_float4(0.f, 0.f, 0.f, 0.f);
            int gc = bn + nq;
            if (gc + 3 < N) v = *(const float4*)(B + (size_t)(k0 + row) * N + gc);
            *(float4*)&Bs[row][nq] = v;
        }
        __syncthreads();

#pragma unroll
        for (int kk = 0; kk < BK; kk++) {
            // 4 packed row-pairs of A: one LDS.64 each (m-contiguous, 8B aligned)
            unsigned long long apair[4];
#pragma unroll
            for (int ip = 0; ip < 4; ip++)
                apair[ip] = *(const unsigned long long*)&As[kk][tr + 2 * ip];
            // 4 broadcast-packed B scalars: (b, b)
            unsigned long long bb[4];
#pragma unroll
            for (int j = 0; j < 4; j++) {
                float b = Bs[kk][tc + j];
                asm("mov.b64 %0, {%1, %1};" : "=l"(bb[j]) : "f"(b));
            }
            // 16 packed FMAs = 32 fp32 FMAs
#pragma unroll
            for (int ip = 0; ip < 4; ip++)
#pragma unroll
                for (int j = 0; j < 4; j++)
                    asm("fma.rn.f32x2 %0, %1, %2, %0;"
                        : "+l"(acc2[ip][j]) : "l"(apair[ip]), "l"(bb[j]));
        }
        __syncthreads();
    }

#pragma unroll
    for (int ip = 0; ip < 4; ip++) {
        int r0 = bm + tr + 2 * ip;
        float s0 = 0.f, s1 = 0.f;
        if (EPI == 0) {
            if (r0 < M)     { float d = g_dinv[r0];     s0 = d * d; }
            if (r0 + 1 < M) { float d = g_dinv[r0 + 1]; s1 = d * d; }
        }
#pragma unroll
        for (int j = 0; j < 4; j++) {
            int c = bn + tc + j;
            if (c >= N) continue;
            float lo, hi;
            asm("mov.b64 {%0, %1}, %2;" : "=f"(lo), "=f"(hi) : "l"(acc2[ip][j]));
            if (EPI == 0) {
                if (r0 < M) {
                    C [(size_t)r0 * N + c] = lo;
                    C2[(size_t)r0 * N + c] = lo * s0;
                }
                if (r0 + 1 < M) {
                    C [(size_t)(r0 + 1) * N + c] = hi;
                    C2[(size_t)(r0 + 1) * N + c] = hi * s1;
                }
            } else {
                float bc = bias[c];
                if (r0 < M)     C[(size_t)r0 * N + c]       = lo + bc;
                if (r0 + 1 < M) C[(size_t)(r0 + 1) * N + c] = hi + bc;
            }
        }
    }
}

// ---------------------------------------------------------------------------
// relu(out1 + b1) -> r1, and init agg2 = r1 * dinv^2 (self-loop of layer 2)
// ---------------------------------------------------------------------------
__global__ void k_relu_agg2init(const float* __restrict__ b1) {
    const int TOT4 = NN * (H1D / 4);
    int i4 = blockIdx.x * blockDim.x + threadIdx.x;
    if (i4 >= TOT4) return;
    int node = i4 / (H1D / 4);
    int f4   = i4 - node * (H1D / 4);
    float4 v  = *((const float4*)g_out1 + i4);
    float4 bb = *((const float4*)b1 + f4);
    v.x = fmaxf(v.x + bb.x, 0.f);
    v.y = fmaxf(v.y + bb.y, 0.f);
    v.z = fmaxf(v.z + bb.z, 0.f);
    v.w = fmaxf(v.w + bb.w, 0.f);
    *((float4*)g_r1 + i4) = v;
    float d = g_dinv[node];
    float s = d * d;
    float4 w = make_float4(v.x * s, v.y * s, v.z * s, v.w * s);
    *((float4*)g_agg2 + i4) = w;
}

// ---------------------------------------------------------------------------
// Edge scatter: one warp per edge. Out[dst] += Hin[src] * dinv[src]*dinv[dst]
// 400 floats/row = 100 float4 -> red.global.add.v4.f32 (sm_90+)
// ---------------------------------------------------------------------------
__global__ __launch_bounds__(256)
void k_scatter(const void* __restrict__ ei,
               const float* __restrict__ Hin,
               float* __restrict__ Out, int E)
{
    int g    = blockIdx.x * blockDim.x + threadIdx.x;
    int e    = g >> 5;
    int lane = g & 31;
    if (e >= E) return;
    int s = edge_at(ei, e);
    int d = edge_at(ei, (long long)E + e);
    if ((unsigned)s >= NN || (unsigned)d >= NN) return;
    float norm = g_dinv[s] * g_dinv[d];
    const float4* hp = (const float4*)(Hin + (size_t)s * H1D);
    float4*       op = (float4*)(Out + (size_t)d * H1D);
#pragma unroll 1
    for (int q = lane; q < H1D / 4; q += 32) {
        float4 v = hp[q];
        asm volatile("red.global.add.v4.f32 [%0], {%1, %2, %3, %4};"
                     :: "l"(op + q),
                        "f"(v.x * norm), "f"(v.y * norm),
                        "f"(v.z * norm), "f"(v.w * norm)
                     : "memory");
    }
}

// ---------------------------------------------------------------------------
extern "C" void kernel_launch(void* const* d_in, const int* in_sizes, int n_in,
                              void* d_out, int out_size)
{
    const float* x  = (const float*)d_in[0];
    const void*  ei = d_in[1];                  // int32 OR int64 — probed on device
    const float* W1 = (const float*)d_in[2];
    const float* b1 = (const float*)d_in[3];
    const float* W2 = (const float*)d_in[4];
    const float* b2 = (const float*)d_in[5];
    float* out = (float*)d_out;

    int E = in_sizes[1] / 2;   // element count of edge_index / 2, dtype-independent

    float *pH1, *pOut1, *pR1, *pAgg2;
    cudaGetSymbolAddress((void**)&pH1,   g_H1);
    cudaGetSymbolAddress((void**)&pOut1, g_out1);
    cudaGetSymbolAddress((void**)&pR1,   g_r1);
    cudaGetSymbolAddress((void**)&pAgg2, g_agg2);

    // 0) probe edge_index dtype (deterministic)
    k_detect<<<1, 1>>>((const int*)ei, in_sizes[1]);

    // 1) degrees + normalization
    k_zero_deg<<<(NN + 255) / 256, 256>>>();
    k_count<<<(E + 255) / 256, 256>>>(ei, E);
    k_dinv<<<(NN + 255) / 256, 256>>>();

    // 2) H1 = x @ W1 ; out1 initialized with self-loop term H1*dinv^2
    dim3 g1((H1D + 63) / 64, (NN + 127) / 128);
    k_sgemm<0><<<g1, 256>>>(x, W1, pH1, pOut1, nullptr, NN, H1D, INCH);

    // 3) edge aggregation for layer 1
    int sblocks = (int)(((long long)E * 32 + 255) / 256);
    k_scatter<<<sblocks, 256>>>(ei, pH1, pOut1, E);

    // 4) relu + bias ; init agg2 with self-loop term
    k_relu_agg2init<<<(NN * (H1D / 4) + 255) / 256, 256>>>(b1);

    // 5) edge aggregation for layer 2 (on 400 features — BEFORE the GEMM,
    //    exploiting linearity: S(r1) @ W2 == S(r1 @ W2))
    k_scatter<<<sblocks, 256>>>(ei, pR1, pAgg2, E);

    // 6) out = agg2 @ W2 + b2
    dim3 g2((H2D + 63) / 64, (NN + 127) / 128);
    k_sgemm<1><<<g2, 256>>>(pAgg2, W2, out, nullptr, b2, NN, H2D, H1D);
}

// round 7
// speedup vs baseline: 1.1837x; 1.1200x over previous
#include <cuda_runtime.h>
#include <cuda_bf16.h>
#include <cstdint>
#include <cstddef>

#define NN   50000
#define MPAD 50048          // 391 * 128
#define INCH 512
#define H1D  400
#define H2D  800
#define K1P  512            // padded K for GEMM1
#define K2P  448            // padded K for GEMM2
#define N1P  512            // padded N (buffer) for GEMM1
#define N2P  896            // padded N (buffer) for GEMM2

// ---------------- fp32 scratch ----------------
__device__ float g_H1  [(size_t)NN * H1D];
__device__ float g_out1[(size_t)NN * H1D];
__device__ float g_r1  [(size_t)NN * H1D];
__device__ float g_agg2[(size_t)NN * H1D];
__device__ float g_dinv[NN];
__device__ int   g_deg [NN];
__device__ int   g_is64;

// ---------------- bf16 split scratch (zero-padded) ----------------
__device__ __nv_bfloat16 g_xh [(size_t)MPAD * K1P];
__device__ __nv_bfloat16 g_xl [(size_t)MPAD * K1P];
__device__ __nv_bfloat16 g_a2h[(size_t)MPAD * K2P];
__device__ __nv_bfloat16 g_a2l[(size_t)MPAD * K2P];
__device__ __nv_bfloat16 g_w1h[(size_t)N1P * K1P];   // W1^T  [N,K] K-major
__device__ __nv_bfloat16 g_w1l[(size_t)N1P * K1P];
__device__ __nv_bfloat16 g_w2h[(size_t)N2P * K2P];   // W2^T
__device__ __nv_bfloat16 g_w2l[(size_t)N2P * K2P];

// ---------------------------------------------------------------------------
// Edge-index dtype probe: int64 payloads (<50000) have all-zero odd words.
// ---------------------------------------------------------------------------
__global__ void k_detect(const int* __restrict__ w, int nwords) {
    if (threadIdx.x == 0 && blockIdx.x == 0) {
        int lim = nwords < 4096 ? nwords : 4096;
        int is64 = 1;
        for (int i = 1; i < lim; i += 2)
            if (w[i] != 0) { is64 = 0; break; }
        g_is64 = is64;
    }
}
__device__ __forceinline__ int edge_at(const void* ei, long long idx) {
    if (g_is64) return (int)((const long long*)ei)[idx];
    return ((const int*)ei)[idx];
}

// ---------------------------------------------------------------------------
// Degree / normalization
// ---------------------------------------------------------------------------
__global__ void k_zero_deg() {
    int i = blockIdx.x * blockDim.x + threadIdx.x;
    if (i < NN) g_deg[i] = 0;
}
__global__ void k_count(const void* __restrict__ ei, int E) {
    int e = blockIdx.x * blockDim.x + threadIdx.x;
    if (e >= E) return;
    int d = edge_at(ei, (long long)E + e);
    if ((unsigned)d < NN) atomicAdd(&g_deg[d], 1);
}
__global__ void k_dinv() {
    int i = blockIdx.x * blockDim.x + threadIdx.x;
    if (i < NN) g_dinv[i] = rsqrtf((float)g_deg[i] + 1.0f);
}

// ---------------------------------------------------------------------------
// fp32 -> bf16 hi/lo split, row-major [M,Ks] -> padded [MPAD,Kp], zero-filled.
// ---------------------------------------------------------------------------
__global__ void k_splitA(const float* __restrict__ src,
                         __nv_bfloat16* __restrict__ dh,
                         __nv_bfloat16* __restrict__ dl,
                         int M, int Ks, int Kp)
{
    long long tot = (long long)MPAD * (Kp >> 1);
    long long i2 = (long long)blockIdx.x * blockDim.x + threadIdx.x;
    if (i2 >= tot) return;
    int r  = (int)(i2 / (Kp >> 1));
    int c2 = (int)(i2 - (long long)r * (Kp >> 1)) * 2;
    float v0 = 0.f, v1 = 0.f;
    if (r < M) {
        if (c2     < Ks) v0 = src[(size_t)r * Ks + c2];
        if (c2 + 1 < Ks) v1 = src[(size_t)r * Ks + c2 + 1];
    }
    __nv_bfloat16 h0 = __float2bfloat16(v0), h1 = __float2bfloat16(v1);
    __nv_bfloat162 H, L;
    H.x = h0; H.y = h1;
    L.x = __float2bfloat16(v0 - __bfloat162float(h0));
    L.y = __float2bfloat16(v1 - __bfloat162float(h1));
    *(__nv_bfloat162*)(dh + (size_t)r * Kp + c2) = H;
    *(__nv_bfloat162*)(dl + (size_t)r * Kp + c2) = L;
}

// W [K,N] row-major -> transposed padded bf16 hi/lo [Np, Kp]
__global__ void k_splitB(const float* __restrict__ W,
                         __nv_bfloat16* __restrict__ dh,
                         __nv_bfloat16* __restrict__ dl,
                         int K, int N, int Kp, int Np)
{
    int idx = blockIdx.x * blockDim.x + threadIdx.x;
    if (idx >= Np * Kp) return;
    int n = idx / Kp, k = idx - n * Kp;
    float v = (n < N && k < K) ? W[(size_t)k * N + n] : 0.f;
    __nv_bfloat16 h = __float2bfloat16(v);
    dh[idx] = h;
    dl[idx] = __float2bfloat16(v - __bfloat162float(h));
}

// ---------------------------------------------------------------------------
// Split-bf16 GEMM via mma.sync m16n8k16 (HMMA, baseline PTX -- works on sm_103).
// C[M,Nreal] = A @ B^T ; A=[MPAD,Kp] hi/lo bf16, B^T=[Np,Kp] hi/lo bf16.
// acc += Ah*Bh + Ah*Bl + Al*Bh  (fp32 accumulate; al*bl dropped, ~2^-16 rel)
// CTA tile 128x64, BK=32, 8 warps (4m x 2n), warp tile 32x32.
// EPI==0: C = acc, C2 = acc * dinv[row]^2 ; EPI==1: C = acc + bias[col]
// ---------------------------------------------------------------------------
#define MMA_BF16(c, a, b) \
    asm volatile("mma.sync.aligned.m16n8k16.row.col.f32.bf16.bf16.f32 " \
        "{%0,%1,%2,%3}, {%4,%5,%6,%7}, {%8,%9}, {%0,%1,%2,%3};" \
        : "+f"((c)[0]), "+f"((c)[1]), "+f"((c)[2]), "+f"((c)[3]) \
        : "r"((a)[0]), "r"((a)[1]), "r"((a)[2]), "r"((a)[3]), \
          "r"((b)[0]), "r"((b)[1]))

#define APAD 40   // 32 + 8 bf16 padding: conflict-free fragment loads

template<int EPI>
__global__ __launch_bounds__(256)
void mma_gemm(const __nv_bfloat16* __restrict__ Ah, const __nv_bfloat16* __restrict__ Al,
              const __nv_bfloat16* __restrict__ Bh, const __nv_bfloat16* __restrict__ Bl,
              float* __restrict__ C, float* __restrict__ C2,
              const float* __restrict__ bias, int Kp, int Nreal)
{
    __shared__ __nv_bfloat16 As_h[128][APAD], As_l[128][APAD];
    __shared__ __nv_bfloat16 Bs_h[64][APAD],  Bs_l[64][APAD];

    int tid  = threadIdx.x;
    int lane = tid & 31, wid = tid >> 5;
    int wm = wid & 3;          // 0..3 : m offset wm*32
    int wn = wid >> 2;         // 0..1 : n offset wn*32
    int bm = blockIdx.y * 128;
    int bn = blockIdx.x * 64;
    int r  = lane >> 2;        // 0..7
    int q2 = (lane & 3) * 2;   // 0,2,4,6

    float acc[2][4][4];
#pragma unroll
    for (int mt = 0; mt < 2; mt++)
#pragma unroll
        for (int nt = 0; nt < 4; nt++)
#pragma unroll
            for (int j = 0; j < 4; j++) acc[mt][nt][j] = 0.f;

    for (int k0 = 0; k0 < Kp; k0 += 32) {
        // ---- load A tile: 128 rows x 32 k (each thread: one 32B half-row) ----
        {
            int row  = tid >> 1;
            int half = (tid & 1) * 16;
            const uint4* gh = (const uint4*)(Ah + (size_t)(bm + row) * Kp + k0 + half);
            const uint4* gl = (const uint4*)(Al + (size_t)(bm + row) * Kp + k0 + half);
            uint4* sh = (uint4*)&As_h[row][half];
            uint4* sl = (uint4*)&As_l[row][half];
            sh[0] = gh[0]; sh[1] = gh[1];
            sl[0] = gl[0]; sl[1] = gl[1];
        }
        // ---- load B tile: 64 rows x 32 k ----
        if (tid < 128) {
            int row  = tid >> 1;
            int half = (tid & 1) * 16;
            const uint4* gh = (const uint4*)(Bh + (size_t)(bn + row) * Kp + k0 + half);
            const uint4* gl = (const uint4*)(Bl + (size_t)(bn + row) * Kp + k0 + half);
            uint4* sh = (uint4*)&Bs_h[row][half];
            uint4* sl = (uint4*)&Bs_l[row][half];
            sh[0] = gh[0]; sh[1] = gh[1];
            sl[0] = gl[0]; sl[1] = gl[1];
        }
        __syncthreads();

#pragma unroll
        for (int ks = 0; ks < 32; ks += 16) {
            uint32_t ah[2][4], al[2][4], bh[4][2], bl[4][2];
#pragma unroll
            for (int mt = 0; mt < 2; mt++) {
                int mrow = wm * 32 + mt * 16 + r;
                ah[mt][0] = *(const uint32_t*)&As_h[mrow    ][ks + q2];
                ah[mt][1] = *(const uint32_t*)&As_h[mrow + 8][ks + q2];
                ah[mt][2] = *(const uint32_t*)&As_h[mrow    ][ks + q2 + 8];
                ah[mt][3] = *(const uint32_t*)&As_h[mrow + 8][ks + q2 + 8];
                al[mt][0] = *(const uint32_t*)&As_l[mrow    ][ks + q2];
                al[mt][1] = *(const uint32_t*)&As_l[mrow + 8][ks + q2];
                al[mt][2] = *(const uint32_t*)&As_l[mrow    ][ks + q2 + 8];
                al[mt][3] = *(const uint32_t*)&As_l[mrow + 8][ks + q2 + 8];
            }
#pragma unroll
            for (int nt = 0; nt < 4; nt++) {
                int nrow = wn * 32 + nt * 8 + r;
                bh[nt][0] = *(const uint32_t*)&Bs_h[nrow][ks + q2];
                bh[nt][1] = *(const uint32_t*)&Bs_h[nrow][ks + q2 + 8];
                bl[nt][0] = *(const uint32_t*)&Bs_l[nrow][ks + q2];
                bl[nt][1] = *(const uint32_t*)&Bs_l[nrow][ks + q2 + 8];
            }
#pragma unroll
            for (int mt = 0; mt < 2; mt++)
#pragma unroll
                for (int nt = 0; nt < 4; nt++) {
                    MMA_BF16(acc[mt][nt], ah[mt], bh[nt]);
                    MMA_BF16(acc[mt][nt], ah[mt], bl[nt]);
                    MMA_BF16(acc[mt][nt], al[mt], bh[nt]);
                }
        }
        __syncthreads();
    }

    // ---- epilogue ----
#pragma unroll
    for (int mt = 0; mt < 2; mt++) {
        int row0 = bm + wm * 32 + mt * 16 + r;   // c0,c1
        int row1 = row0 + 8;                     // c2,c3
        float s0 = 0.f, s1 = 0.f;
        if (EPI == 0) {
            if (row0 < NN) { float d = g_dinv[row0]; s0 = d * d; }
            if (row1 < NN) { float d = g_dinv[row1]; s1 = d * d; }
        }
#pragma unroll
        for (int nt = 0; nt < 4; nt++) {
            int col = bn + wn * 32 + nt * 8 + q2;
            if (col >= Nreal) continue;
            float2 v0 = make_float2(acc[mt][nt][0], acc[mt][nt][1]);
            float2 v1 = make_float2(acc[mt][nt][2], acc[mt][nt][3]);
            if (EPI == 0) {
                if (row0 < NN) {
                    *(float2*)(C  + (size_t)row0 * Nreal + col) = v0;
                    *(float2*)(C2 + (size_t)row0 * Nreal + col) =
                        make_float2(v0.x * s0, v0.y * s0);
                }
                if (row1 < NN) {
                    *(float2*)(C  + (size_t)row1 * Nreal + col) = v1;
                    *(float2*)(C2 + (size_t)row1 * Nreal + col) =
                        make_float2(v1.x * s1, v1.y * s1);
                }
            } else {
                float2 bb = *(const float2*)(bias + col);
                if (row0 < NN)
                    *(float2*)(C + (size_t)row0 * Nreal + col) =
                        make_float2(v0.x + bb.x, v0.y + bb.y);
                if (row1 < NN)
                    *(float2*)(C + (size_t)row1 * Nreal + col) =
                        make_float2(v1.x + bb.x, v1.y + bb.y);
            }
        }
    }
}

// ---------------------------------------------------------------------------
// relu(out1 + b1) -> r1, and init agg2 = r1 * dinv^2 (self-loop of layer 2)
// ---------------------------------------------------------------------------
__global__ void k_relu_agg2init(const float* __restrict__ b1) {
    const int TOT4 = NN * (H1D / 4);
    int i4 = blockIdx.x * blockDim.x + threadIdx.x;
    if (i4 >= TOT4) return;
    int node = i4 / (H1D / 4);
    int f4   = i4 - node * (H1D / 4);
    float4 v  = *((const float4*)g_out1 + i4);
    float4 bb = *((const float4*)b1 + f4);
    v.x = fmaxf(v.x + bb.x, 0.f);
    v.y = fmaxf(v.y + bb.y, 0.f);
    v.z = fmaxf(v.z + bb.z, 0.f);
    v.w = fmaxf(v.w + bb.w, 0.f);
    *((float4*)g_r1 + i4) = v;
    float d = g_dinv[node];
    float s = d * d;
    float4 w = make_float4(v.x * s, v.y * s, v.z * s, v.w * s);
    *((float4*)g_agg2 + i4) = w;
}

// ---------------------------------------------------------------------------
// Edge scatter: one warp per edge. Out[dst] += Hin[src] * dinv[src]*dinv[dst]
// ---------------------------------------------------------------------------
__global__ __launch_bounds__(256)
void k_scatter(const void* __restrict__ ei,
               const float* __restrict__ Hin,
               float* __restrict__ Out, int E)
{
    int g    = blockIdx.x * blockDim.x + threadIdx.x;
    int e    = g >> 5;
    int lane = g & 31;
    if (e >= E) return;
    int s = edge_at(ei, e);
    int d = edge_at(ei, (long long)E + e);
    if ((unsigned)s >= NN || (unsigned)d >= NN) return;
    float norm = g_dinv[s] * g_dinv[d];
    const float4* hp = (const float4*)(Hin + (size_t)s * H1D);
    float4*       op = (float4*)(Out + (size_t)d * H1D);
#pragma unroll 1
    for (int q = lane; q < H1D / 4; q += 32) {
        float4 v = hp[q];
        asm volatile("red.global.add.v4.f32 [%0], {%1, %2, %3, %4};"
                     :: "l"(op + q),
                        "f"(v.x * norm), "f"(v.y * norm),
                        "f"(v.z * norm), "f"(v.w * norm)
                     : "memory");
    }
}

// ---------------------------------------------------------------------------
extern "C" void kernel_launch(void* const* d_in, const int* in_sizes, int n_in,
                              void* d_out, int out_size)
{
    const float* x  = (const float*)d_in[0];
    const void*  ei = d_in[1];
    const float* W1 = (const float*)d_in[2];
    const float* b1 = (const float*)d_in[3];
    const float* W2 = (const float*)d_in[4];
    const float* b2 = (const float*)d_in[5];
    float* out = (float*)d_out;

    int E = in_sizes[1] / 2;

    float *pH1, *pOut1, *pR1, *pAgg2;
    cudaGetSymbolAddress((void**)&pH1,   g_H1);
    cudaGetSymbolAddress((void**)&pOut1, g_out1);
    cudaGetSymbolAddress((void**)&pR1,   g_r1);
    cudaGetSymbolAddress((void**)&pAgg2, g_agg2);
    __nv_bfloat16 *pxh, *pxl, *pa2h, *pa2l, *pw1h, *pw1l, *pw2h, *pw2l;
    cudaGetSymbolAddress((void**)&pxh,  g_xh);
    cudaGetSymbolAddress((void**)&pxl,  g_xl);
    cudaGetSymbolAddress((void**)&pa2h, g_a2h);
    cudaGetSymbolAddress((void**)&pa2l, g_a2l);
    cudaGetSymbolAddress((void**)&pw1h, g_w1h);
    cudaGetSymbolAddress((void**)&pw1l, g_w1l);
    cudaGetSymbolAddress((void**)&pw2h, g_w2h);
    cudaGetSymbolAddress((void**)&pw2l, g_w2l);

    // 0) probe edge_index dtype
    k_detect<<<1, 1>>>((const int*)ei, in_sizes[1]);

    // 1) degrees + normalization
    k_zero_deg<<<(NN + 255) / 256, 256>>>();
    k_count<<<(E + 255) / 256, 256>>>(ei, E);
    k_dinv<<<(NN + 255) / 256, 256>>>();

    // 2) split x and W1 into bf16 hi/lo (padded)
    {
        long long tot = (long long)MPAD * (K1P / 2);
        k_splitA<<<(int)((tot + 255) / 256), 256>>>(x, pxh, pxl, NN, INCH, K1P);
        k_splitB<<<(N1P * K1P + 255) / 256, 256>>>(W1, pw1h, pw1l, INCH, H1D, K1P, N1P);
    }

    // 3) H1 = x @ W1 (split-bf16 HMMA); out1 = H1 * dinv^2
    mma_gemm<0><<<dim3((H1D + 63) / 64, MPAD / 128), 256>>>(
        pxh, pxl, pw1h, pw1l, pH1, pOut1, nullptr, K1P, H1D);

    // 4) edge aggregation for layer 1
    int sblocks = (int)(((long long)E * 32 + 255) / 256);
    k_scatter<<<sblocks, 256>>>(ei, pH1, pOut1, E);

    // 5) relu + bias ; init agg2 with self-loop term
    k_relu_agg2init<<<(NN * (H1D / 4) + 255) / 256, 256>>>(b1);

    // 6) edge aggregation for layer 2 (pre-GEMM, exploiting linearity)
    k_scatter<<<sblocks, 256>>>(ei, pR1, pAgg2, E);

    // 7) split agg2 and W2
    {
        long long tot = (long long)MPAD * (K2P / 2);
        k_splitA<<<(int)((tot + 255) / 256), 256>>>(pAgg2, pa2h, pa2l, NN, H1D, K2P);
        k_splitB<<<(N2P * K2P + 255) / 256, 256>>>(W2, pw2h, pw2l, H1D, H2D, K2P, N2P);
    }

    // 8) out = agg2 @ W2 + b2
    mma_gemm<1><<<dim3((H2D + 63) / 64, MPAD / 128), 256>>>(
        pa2h, pa2l, pw2h, pw2l, out, nullptr, b2, K2P, H2D);
}

// round 10
// speedup vs baseline: 1.7998x; 1.5204x over previous
#include <cuda_runtime.h>
#include <cuda_bf16.h>
#include <cstdint>
#include <cstddef>

#define NN   50000
#define MPAD 50048          // 391 * 128
#define INCH 512
#define H1D  400
#define H2D  800
#define K1P  512            // padded K for GEMM1
#define K2P  448            // padded K for GEMM2
#define N1P  512            // padded N (buffer) for GEMM1
#define N2P  896            // padded N (buffer) for GEMM2
#define EMAX 1700000

// ---------------- fp32 scratch ----------------
__device__ float g_H1  [(size_t)NN * H1D];
__device__ float g_r1  [(size_t)NN * H1D];
__device__ float g_dinv[NN];
__device__ int   g_deg [NN];
__device__ int   g_off [NN + 1];
__device__ int   g_cur [NN];
__device__ int   g_csrc [EMAX];
__device__ float g_cnorm[EMAX];
__device__ int   g_is64;

// ---------------- bf16 split scratch (zero-padded; pads never written) ------
__device__ __nv_bfloat16 g_xh [(size_t)MPAD * K1P];
__device__ __nv_bfloat16 g_xl [(size_t)MPAD * K1P];
__device__ __nv_bfloat16 g_a2h[(size_t)MPAD * K2P];
__device__ __nv_bfloat16 g_a2l[(size_t)MPAD * K2P];
__device__ __nv_bfloat16 g_w1h[(size_t)N1P * K1P];   // W1^T  [N,K] K-major
__device__ __nv_bfloat16 g_w1l[(size_t)N1P * K1P];
__device__ __nv_bfloat16 g_w2h[(size_t)N2P * K2P];   // W2^T
__device__ __nv_bfloat16 g_w2l[(size_t)N2P * K2P];

// ---------------------------------------------------------------------------
// init: zero degrees + assume int64 until a nonzero odd word is found
// ---------------------------------------------------------------------------
__global__ void k_init() {
    int i = blockIdx.x * blockDim.x + threadIdx.x;
    if (i < NN) g_deg[i] = 0;
    if (i == 0) g_is64 = 1;
}
__global__ void k_detectP(const int* __restrict__ w, int nwords) {
    int i = (blockIdx.x * blockDim.x + threadIdx.x) * 2 + 1;
    int lim = nwords < 4096 ? nwords : 4096;
    if (i < lim && w[i] != 0) g_is64 = 0;
}
__device__ __forceinline__ int edge_at(const void* ei, long long idx) {
    if (g_is64) return (int)((const long long*)ei)[idx];
    return ((const int*)ei)[idx];
}

// ---------------------------------------------------------------------------
// Degree / normalization
// ---------------------------------------------------------------------------
__global__ void k_count(const void* __restrict__ ei, int E) {
    int e = blockIdx.x * blockDim.x + threadIdx.x;
    if (e >= E) return;
    int d = edge_at(ei, (long long)E + e);
    if ((unsigned)d < NN) atomicAdd(&g_deg[d], 1);
}
__global__ void k_dinv() {
    int i = blockIdx.x * blockDim.x + threadIdx.x;
    if (i < NN) g_dinv[i] = rsqrtf((float)g_deg[i] + 1.0f);
}

// ---------------------------------------------------------------------------
// Exclusive scan of degrees -> g_off (NN+1), cursor copy -> g_cur.
// Single block, 1024 threads, Hillis-Steele over 1024-tiles with carry.
// ---------------------------------------------------------------------------
__global__ __launch_bounds__(1024)
void k_scan() {
    __shared__ int sh[1024];
    __shared__ int carry;
    int tid = threadIdx.x;
    if (tid == 0) carry = 0;
    __syncthreads();
    for (int base = 0; base < NN; base += 1024) {
        int i = base + tid;
        int v = (i < NN) ? g_deg[i] : 0;
        sh[tid] = v;
        __syncthreads();
#pragma unroll
        for (int off = 1; off < 1024; off <<= 1) {
            int t = (tid >= off) ? sh[tid - off] : 0;
            __syncthreads();
            sh[tid] += t;
            __syncthreads();
        }
        if (i < NN) {
            int excl = carry + sh[tid] - v;
            g_off[i] = excl;
            g_cur[i] = excl;
        }
        __syncthreads();
        if (tid == 0) carry += sh[1023];
        __syncthreads();
    }
    if (tid == 0) g_off[NN] = carry;
}

// ---------------------------------------------------------------------------
// CSR placement: csrc[pos]=src, cnorm[pos]=dinv[s]*dinv[d] for pos in dst list
// ---------------------------------------------------------------------------
__global__ void k_place(const void* __restrict__ ei, int E) {
    int e = blockIdx.x * blockDim.x + threadIdx.x;
    if (e >= E) return;
    int s = edge_at(ei, e);
    int d = edge_at(ei, (long long)E + e);
    if ((unsigned)s >= NN || (unsigned)d >= NN) return;
    int pos = atomicAdd(&g_cur[d], 1);
    if (pos < EMAX) {
        g_csrc[pos]  = s;
        g_cnorm[pos] = g_dinv[s] * g_dinv[d];
    }
}

// ---------------------------------------------------------------------------
// fp32 -> bf16 hi/lo split, row-major [M,Ks] -> padded [MPAD,Kp], zero-filled.
// ---------------------------------------------------------------------------
__global__ void k_splitA(const float* __restrict__ src,
                         __nv_bfloat16* __restrict__ dh,
                         __nv_bfloat16* __restrict__ dl,
                         int M, int Ks, int Kp)
{
    long long tot = (long long)MPAD * (Kp >> 1);
    long long i2 = (long long)blockIdx.x * blockDim.x + threadIdx.x;
    if (i2 >= tot) return;
    int r  = (int)(i2 / (Kp >> 1));
    int c2 = (int)(i2 - (long long)r * (Kp >> 1)) * 2;
    float v0 = 0.f, v1 = 0.f;
    if (r < M) {
        if (c2     < Ks) v0 = src[(size_t)r * Ks + c2];
        if (c2 + 1 < Ks) v1 = src[(size_t)r * Ks + c2 + 1];
    }
    __nv_bfloat16 h0 = __float2bfloat16(v0), h1 = __float2bfloat16(v1);
    __nv_bfloat162 H, L;
    H.x = h0; H.y = h1;
    L.x = __float2bfloat16(v0 - __bfloat162float(h0));
    L.y = __float2bfloat16(v1 - __bfloat162float(h1));
    *(__nv_bfloat162*)(dh + (size_t)r * Kp + c2) = H;
    *(__nv_bfloat162*)(dl + (size_t)r * Kp + c2) = L;
}

// W [K,N] row-major -> transposed padded bf16 hi/lo [Np, Kp]
__global__ void k_splitB(const float* __restrict__ W,
                         __nv_bfloat16* __restrict__ dh,
                         __nv_bfloat16* __restrict__ dl,
                         int K, int N, int Kp, int Np)
{
    int idx = blockIdx.x * blockDim.x + threadIdx.x;
    if (idx >= Np * Kp) return;
    int n = idx / Kp, k = idx - n * Kp;
    float v = (n < N && k < K) ? W[(size_t)k * N + n] : 0.f;
    __nv_bfloat16 h = __float2bfloat16(v);
    dh[idx] = h;
    dl[idx] = __float2bfloat16(v - __bfloat162float(h));
}

// ---------------------------------------------------------------------------
// Split-bf16 GEMM via mma.sync m16n8k16 (baseline PTX, sm_103-safe).
// acc += Ah*Bh + Ah*Bl + Al*Bh  (fp32 acc; al*bl dropped, ~2^-16 rel)
// CTA tile 128x64, BK=32, 8 warps (4m x 2n).
// EPI==0: C = acc ; EPI==1: C = acc + bias[col]
// ---------------------------------------------------------------------------
#define MMA_BF16(c, a, b) \
    asm volatile("mma.sync.aligned.m16n8k16.row.col.f32.bf16.bf16.f32 " \
        "{%0,%1,%2,%3}, {%4,%5,%6,%7}, {%8,%9}, {%0,%1,%2,%3};" \
        : "+f"((c)[0]), "+f"((c)[1]), "+f"((c)[2]), "+f"((c)[3]) \
        : "r"((a)[0]), "r"((a)[1]), "r"((a)[2]), "r"((a)[3]), \
          "r"((b)[0]), "r"((b)[1]))

#define APAD 40

template<int EPI>
__global__ __launch_bounds__(256)
void mma_gemm(const __nv_bfloat16* __restrict__ Ah, const __nv_bfloat16* __restrict__ Al,
              const __nv_bfloat16* __restrict__ Bh, const __nv_bfloat16* __restrict__ Bl,
              float* __restrict__ C, const float* __restrict__ bias,
              int Kp, int Nreal)
{
    __shared__ __nv_bfloat16 As_h[128][APAD], As_l[128][APAD];
    __shared__ __nv_bfloat16 Bs_h[64][APAD],  Bs_l[64][APAD];

    int tid  = threadIdx.x;
    int lane = tid & 31, wid = tid >> 5;
    int wm = wid & 3;
    int wn = wid >> 2;
    int bm = blockIdx.y * 128;
    int bn = blockIdx.x * 64;
    int r  = lane >> 2;
    int q2 = (lane & 3) * 2;

    float acc[2][4][4];
#pragma unroll
    for (int mt = 0; mt < 2; mt++)
#pragma unroll
        for (int nt = 0; nt < 4; nt++)
#pragma unroll
            for (int j = 0; j < 4; j++) acc[mt][nt][j] = 0.f;

    for (int k0 = 0; k0 < Kp; k0 += 32) {
        {
            int row  = tid >> 1;
            int half = (tid & 1) * 16;
            const uint4* gh = (const uint4*)(Ah + (size_t)(bm + row) * Kp + k0 + half);
            const uint4* gl = (const uint4*)(Al + (size_t)(bm + row) * Kp + k0 + half);
            uint4* sh = (uint4*)&As_h[row][half];
            uint4* sl = (uint4*)&As_l[row][half];
            sh[0] = gh[0]; sh[1] = gh[1];
            sl[0] = gl[0]; sl[1] = gl[1];
        }
        if (tid < 128) {
            int row  = tid >> 1;
            int half = (tid & 1) * 16;
            const uint4* gh = (const uint4*)(Bh + (size_t)(bn + row) * Kp + k0 + half);
            const uint4* gl = (const uint4*)(Bl + (size_t)(bn + row) * Kp + k0 + half);
            uint4* sh = (uint4*)&Bs_h[row][half];
            uint4* sl = (uint4*)&Bs_l[row][half];
            sh[0] = gh[0]; sh[1] = gh[1];
            sl[0] = gl[0]; sl[1] = gl[1];
        }
        __syncthreads();

#pragma unroll
        for (int ks = 0; ks < 32; ks += 16) {
            uint32_t ah[2][4], al[2][4], bh[4][2], bl[4][2];
#pragma unroll
            for (int mt = 0; mt < 2; mt++) {
                int mrow = wm * 32 + mt * 16 + r;
                ah[mt][0] = *(const uint32_t*)&As_h[mrow    ][ks + q2];
                ah[mt][1] = *(const uint32_t*)&As_h[mrow + 8][ks + q2];
                ah[mt][2] = *(const uint32_t*)&As_h[mrow    ][ks + q2 + 8];
                ah[mt][3] = *(const uint32_t*)&As_h[mrow + 8][ks + q2 + 8];
                al[mt][0] = *(const uint32_t*)&As_l[mrow    ][ks + q2];
                al[mt][1] = *(const uint32_t*)&As_l[mrow + 8][ks + q2];
                al[mt][2] = *(const uint32_t*)&As_l[mrow    ][ks + q2 + 8];
                al[mt][3] = *(const uint32_t*)&As_l[mrow + 8][ks + q2 + 8];
            }
#pragma unroll
            for (int nt = 0; nt < 4; nt++) {
                int nrow = wn * 32 + nt * 8 + r;
                bh[nt][0] = *(const uint32_t*)&Bs_h[nrow][ks + q2];
                bh[nt][1] = *(const uint32_t*)&Bs_h[nrow][ks + q2 + 8];
                bl[nt][0] = *(const uint32_t*)&Bs_l[nrow][ks + q2];
                bl[nt][1] = *(const uint32_t*)&Bs_l[nrow][ks + q2 + 8];
            }
#pragma unroll
            for (int mt = 0; mt < 2; mt++)
#pragma unroll
                for (int nt = 0; nt < 4; nt++) {
                    MMA_BF16(acc[mt][nt], ah[mt], bh[nt]);
                    MMA_BF16(acc[mt][nt], ah[mt], bl[nt]);
                    MMA_BF16(acc[mt][nt], al[mt], bh[nt]);
                }
        }
        __syncthreads();
    }

#pragma unroll
    for (int mt = 0; mt < 2; mt++) {
        int row0 = bm + wm * 32 + mt * 16 + r;
        int row1 = row0 + 8;
#pragma unroll
        for (int nt = 0; nt < 4; nt++) {
            int col = bn + wn * 32 + nt * 8 + q2;
            if (col >= Nreal) continue;
            float2 v0 = make_float2(acc[mt][nt][0], acc[mt][nt][1]);
            float2 v1 = make_float2(acc[mt][nt][2], acc[mt][nt][3]);
            if (EPI == 1) {
                float2 bb = *(const float2*)(bias + col);
                v0.x += bb.x; v0.y += bb.y;
                v1.x += bb.x; v1.y += bb.y;
            }
            if (row0 < NN) *(float2*)(C + (size_t)row0 * Nreal + col) = v0;
            if (row1 < NN) *(float2*)(C + (size_t)row1 * Nreal + col) = v1;
        }
    }
}

// ---------------------------------------------------------------------------
// Pull aggregation, one block (128 thr = 4 warps = 4 feature chunks) per node.
// PASS==1: in=g_H1 ; out r1 = relu(self+Σ+b1)
// PASS==2: in=g_r1 ; out a2h/a2l = bf16 hi/lo split of (self+Σ)
// ---------------------------------------------------------------------------
template<int PASS>
__global__ __launch_bounds__(128)
void k_pull(const float* __restrict__ b1)
{
    int n = blockIdx.x;
    int q = threadIdx.x;              // float4 index 0..127
    bool act = q < (H1D / 4);

    const float* In = (PASS == 1) ? g_H1 : g_r1;
    float din = g_dinv[n];
    float s2  = din * din;

    float4 acc = make_float4(0.f, 0.f, 0.f, 0.f);
    if (act) {
        float4 v = *((const float4*)(In + (size_t)n * H1D) + q);
        acc = make_float4(v.x * s2, v.y * s2, v.z * s2, v.w * s2);
    }

    int beg = g_off[n], end = g_off[n + 1];
#pragma unroll 2
    for (int j = beg; j < end; j++) {
        int   s  = g_csrc[j];
        float nm = g_cnorm[j];
        if (act) {
            float4 v = *((const float4*)(In + (size_t)s * H1D) + q);
            acc.x += v.x * nm; acc.y += v.y * nm;
            acc.z += v.z * nm; acc.w += v.w * nm;
        }
    }

    if (!act) return;
    if (PASS == 1) {
        float4 bb = *((const float4*)b1 + q);
        acc.x = fmaxf(acc.x + bb.x, 0.f);
        acc.y = fmaxf(acc.y + bb.y, 0.f);
        acc.z = fmaxf(acc.z + bb.z, 0.f);
        acc.w = fmaxf(acc.w + bb.w, 0.f);
        *((float4*)(g_r1 + (size_t)n * H1D) + q) = acc;
    } else {
        // bf16 hi/lo split, direct into padded GEMM2 A buffers
        __nv_bfloat16 h0 = __float2bfloat16(acc.x);
        __nv_bfloat16 h1 = __float2bfloat16(acc.y);
        __nv_bfloat16 h2 = __float2bfloat16(acc.z);
        __nv_bfloat16 h3 = __float2bfloat16(acc.w);
        __nv_bfloat162 H0, H1v, L0, L1;
        H0.x = h0; H0.y = h1; H1v.x = h2; H1v.y = h3;
        L0.x = __float2bfloat16(acc.x - __bfloat162float(h0));
        L0.y = __float2bfloat16(acc.y - __bfloat162float(h1));
        L1.x = __float2bfloat16(acc.z - __bfloat162float(h2));
        L1.y = __float2bfloat16(acc.w - __bfloat162float(h3));
        size_t o = (size_t)n * K2P + q * 4;
        *(__nv_bfloat162*)(g_a2h + o)     = H0;
        *(__nv_bfloat162*)(g_a2h + o + 2) = H1v;
        *(__nv_bfloat162*)(g_a2l + o)     = L0;
        *(__nv_bfloat162*)(g_a2l + o + 2) = L1;
    }
}

// ---------------------------------------------------------------------------
extern "C" void kernel_launch(void* const* d_in, const int* in_sizes, int n_in,
                              void* d_out, int out_size)
{
    const float* x  = (const float*)d_in[0];
    const void*  ei = d_in[1];
    const float* W1 = (const float*)d_in[2];
    const float* b1 = (const float*)d_in[3];
    const float* W2 = (const float*)d_in[4];
    const float* b2 = (const float*)d_in[5];
    float* out = (float*)d_out;

    int E = in_sizes[1] / 2;

    float *pH1;
    cudaGetSymbolAddress((void**)&pH1, g_H1);
    __nv_bfloat16 *pxh, *pxl, *pa2h, *pa2l, *pw1h, *pw1l, *pw2h, *pw2l;
    cudaGetSymbolAddress((void**)&pxh,  g_xh);
    cudaGetSymbolAddress((void**)&pxl,  g_xl);
    cudaGetSymbolAddress((void**)&pa2h, g_a2h);
    cudaGetSymbolAddress((void**)&pa2l, g_a2l);
    cudaGetSymbolAddress((void**)&pw1h, g_w1h);
    cudaGetSymbolAddress((void**)&pw1l, g_w1l);
    cudaGetSymbolAddress((void**)&pw2h, g_w2h);
    cudaGetSymbolAddress((void**)&pw2l, g_w2l);

    // 0) init + dtype probe (parallel)
    k_init<<<(NN + 255) / 256, 256>>>();
    k_detectP<<<8, 256>>>((const int*)ei, in_sizes[1]);

    // 1) degrees, dinv, CSR
    k_count<<<(E + 255) / 256, 256>>>(ei, E);
    k_dinv<<<(NN + 255) / 256, 256>>>();
    k_scan<<<1, 1024>>>();
    k_place<<<(E + 255) / 256, 256>>>(ei, E);

    // 2) splits for GEMM inputs
    {
        long long tot = (long long)MPAD * (K1P / 2);
        k_splitA<<<(int)((tot + 255) / 256), 256>>>(x, pxh, pxl, NN, INCH, K1P);
        k_splitB<<<(N1P * K1P + 255) / 256, 256>>>(W1, pw1h, pw1l, INCH, H1D, K1P, N1P);
        k_splitB<<<(N2P * K2P + 255) / 256, 256>>>(W2, pw2h, pw2l, H1D, H2D, K2P, N2P);
    }

    // 3) H1 = x @ W1
    mma_gemm<0><<<dim3((H1D + 63) / 64, MPAD / 128), 256>>>(
        pxh, pxl, pw1h, pw1l, pH1, nullptr, K1P, H1D);

    // 4) pull-aggregate layer 1 + relu + bias  -> r1
    k_pull<1><<<NN, 128>>>(b1);

    // 5) pull-aggregate layer 2 + bf16 split   -> a2h/a2l
    k_pull<2><<<NN, 128>>>(nullptr);

    // 6) out = agg2 @ W2 + b2
    mma_gemm<1><<<dim3((H2D + 63) / 64, MPAD / 128), 256>>>(
        pa2h, pa2l, pw2h, pw2l, out, b2, K2P, H2D);
}

// round 13
// speedup vs baseline: 2.1435x; 1.1910x over previous
#include <cuda_runtime.h>
#include <cuda_bf16.h>
#include <cstdint>
#include <cstddef>

#define NN   50000
#define MPAD 50048          // 391 * 128
#define INCH 512
#define H1D  400
#define H2D  800
#define K1P  512
#define K2P  448
#define N1P  512
#define N2P  896
#define EMAX 1700000

// ---------------- fp32 scratch ----------------
__device__ float g_H1  [(size_t)NN * H1D];
__device__ float g_r1  [(size_t)NN * H1D];
__device__ float g_dinv[NN];
__device__ int   g_deg [NN];
__device__ int   g_off [NN + 1];
__device__ int   g_cur [NN];
__device__ int   g_csrc [EMAX];
__device__ float g_cnorm[EMAX];
__device__ int   g_is64;

// ---------------- bf16 split scratch (zero-padded; pads never written) ------
__device__ __nv_bfloat16 g_xh [(size_t)MPAD * K1P];
__device__ __nv_bfloat16 g_xl [(size_t)MPAD * K1P];
__device__ __nv_bfloat16 g_a2h[(size_t)MPAD * K2P];
__device__ __nv_bfloat16 g_a2l[(size_t)MPAD * K2P];
__device__ __nv_bfloat16 g_w1h[(size_t)N1P * K1P];
__device__ __nv_bfloat16 g_w1l[(size_t)N1P * K1P];
__device__ __nv_bfloat16 g_w2h[(size_t)N2P * K2P];
__device__ __nv_bfloat16 g_w2l[(size_t)N2P * K2P];

// ---------------------------------------------------------------------------
__global__ void k_init() {
    int i = blockIdx.x * blockDim.x + threadIdx.x;
    if (i < NN) g_deg[i] = 0;
    if (i == 0) g_is64 = 1;
}
__global__ void k_detectP(const int* __restrict__ w, int nwords) {
    int i = (blockIdx.x * blockDim.x + threadIdx.x) * 2 + 1;
    int lim = nwords < 4096 ? nwords : 4096;
    if (i < lim && w[i] != 0) g_is64 = 0;
}
__device__ __forceinline__ int edge_at(const void* ei, long long idx) {
    if (g_is64) return (int)((const long long*)ei)[idx];
    return ((const int*)ei)[idx];
}

__global__ void k_count(const void* __restrict__ ei, int E) {
    int e = blockIdx.x * blockDim.x + threadIdx.x;
    if (e >= E) return;
    int d = edge_at(ei, (long long)E + e);
    if ((unsigned)d < NN) atomicAdd(&g_deg[d], 1);
}
__global__ void k_dinv() {
    int i = blockIdx.x * blockDim.x + threadIdx.x;
    if (i < NN) g_dinv[i] = rsqrtf((float)g_deg[i] + 1.0f);
}

// ---------------------------------------------------------------------------
// Exclusive scan via warp shuffles (few barriers).
// ---------------------------------------------------------------------------
__global__ __launch_bounds__(1024)
void k_scan() {
    __shared__ int wsum[32];
    __shared__ int carry;
    int tid = threadIdx.x, lane = tid & 31, wid = tid >> 5;
    if (tid == 0) carry = 0;
    __syncthreads();
    for (int base = 0; base < NN; base += 1024) {
        int i = base + tid;
        int v = (i < NN) ? g_deg[i] : 0;
        int incl = v;
#pragma unroll
        for (int off = 1; off < 32; off <<= 1) {
            int t = __shfl_up_sync(0xffffffffu, incl, off);
            if (lane >= off) incl += t;
        }
        if (lane == 31) wsum[wid] = incl;
        __syncthreads();
        if (wid == 0) {
            int s = wsum[lane];
#pragma unroll
            for (int off = 1; off < 32; off <<= 1) {
                int t = __shfl_up_sync(0xffffffffu, s, off);
                if (lane >= off) s += t;
            }
            wsum[lane] = s;
        }
        __syncthreads();
        int wpre = (wid == 0) ? 0 : wsum[wid - 1];
        int excl = carry + wpre + incl - v;
        if (i < NN) { g_off[i] = excl; g_cur[i] = excl; }
        __syncthreads();
        if (tid == 0) carry += wsum[31];
        __syncthreads();
    }
    if (threadIdx.x == 0) g_off[NN] = carry;
}

__global__ void k_place(const void* __restrict__ ei, int E) {
    int e = blockIdx.x * blockDim.x + threadIdx.x;
    if (e >= E) return;
    int s = edge_at(ei, e);
    int d = edge_at(ei, (long long)E + e);
    if ((unsigned)s >= NN || (unsigned)d >= NN) return;
    int pos = atomicAdd(&g_cur[d], 1);
    if (pos < EMAX) {
        g_csrc[pos]  = s;
        g_cnorm[pos] = g_dinv[s] * g_dinv[d];
    }
}

// ---------------------------------------------------------------------------
// fp32 -> bf16 hi/lo splits
// ---------------------------------------------------------------------------
__global__ void k_splitA(const float* __restrict__ src,
                         __nv_bfloat16* __restrict__ dh,
                         __nv_bfloat16* __restrict__ dl,
                         int M, int Ks, int Kp)
{
    long long tot = (long long)MPAD * (Kp >> 1);
    long long i2 = (long long)blockIdx.x * blockDim.x + threadIdx.x;
    if (i2 >= tot) return;
    int r  = (int)(i2 / (Kp >> 1));
    int c2 = (int)(i2 - (long long)r * (Kp >> 1)) * 2;
    float v0 = 0.f, v1 = 0.f;
    if (r < M) {
        if (c2     < Ks) v0 = src[(size_t)r * Ks + c2];
        if (c2 + 1 < Ks) v1 = src[(size_t)r * Ks + c2 + 1];
    }
    __nv_bfloat16 h0 = __float2bfloat16(v0), h1 = __float2bfloat16(v1);
    __nv_bfloat162 H, L;
    H.x = h0; H.y = h1;
    L.x = __float2bfloat16(v0 - __bfloat162float(h0));
    L.y = __float2bfloat16(v1 - __bfloat162float(h1));
    *(__nv_bfloat162*)(dh + (size_t)r * Kp + c2) = H;
    *(__nv_bfloat162*)(dl + (size_t)r * Kp + c2) = L;
}

__global__ void k_splitB(const float* __restrict__ W,
                         __nv_bfloat16* __restrict__ dh,
                         __nv_bfloat16* __restrict__ dl,
                         int K, int N, int Kp, int Np)
{
    int idx = blockIdx.x * blockDim.x + threadIdx.x;
    if (idx >= Np * Kp) return;
    int n = idx / Kp, k = idx - n * Kp;
    float v = (n < N && k < K) ? W[(size_t)k * N + n] : 0.f;
    __nv_bfloat16 h = __float2bfloat16(v);
    dh[idx] = h;
    dl[idx] = __float2bfloat16(v - __bfloat162float(h));
}

// ---------------------------------------------------------------------------
// Split-bf16 GEMM, cp.async double-buffered + ldmatrix fragments.
// CTA tile 128x128, BK=32, 8 warps (2m x 4n), warp tile 64x32.
// acc += Ah*Bh + Ah*Bl + Al*Bh
// ---------------------------------------------------------------------------
#define MMA_BF16(c, a, b) \
    asm volatile("mma.sync.aligned.m16n8k16.row.col.f32.bf16.bf16.f32 " \
        "{%0,%1,%2,%3}, {%4,%5,%6,%7}, {%8,%9}, {%0,%1,%2,%3};" \
        : "+f"((c)[0]), "+f"((c)[1]), "+f"((c)[2]), "+f"((c)[3]) \
        : "r"((a)[0]), "r"((a)[1]), "r"((a)[2]), "r"((a)[3]), \
          "r"((b)[0]), "r"((b)[1]))

#define APAD 40            // row stride 80B: ldmatrix phases hit all 32 banks
#define TBUF 5120          // 128*40 elements per buffer per stage
#define TBYT 10240         // bytes per buffer per stage
#define GSMEM (8 * TBYT)   // 4 arrays x 2 stages

__device__ __forceinline__ uint32_t smem_u32g(const void* p) {
    uint32_t a;
    asm("{ .reg .u64 t; cvta.to.shared.u64 t, %1; cvt.u32.u64 %0, t; }"
        : "=r"(a) : "l"(p));
    return a;
}
__device__ __forceinline__ void cpa16(uint32_t dst, const void* src) {
    asm volatile("cp.async.cg.shared.global [%0], [%1], 16;"
                 :: "r"(dst), "l"(src) : "memory");
}
__device__ __forceinline__ void ldsm4(uint32_t* r, uint32_t addr) {
    asm volatile("ldmatrix.sync.aligned.m8n8.x4.shared.b16 {%0,%1,%2,%3}, [%4];"
                 : "=r"(r[0]), "=r"(r[1]), "=r"(r[2]), "=r"(r[3]) : "r"(addr));
}

template<int EPI>
__global__ __launch_bounds__(256)
void mma_gemm(const __nv_bfloat16* __restrict__ Ah, const __nv_bfloat16* __restrict__ Al,
              const __nv_bfloat16* __restrict__ Bh, const __nv_bfloat16* __restrict__ Bl,
              float* __restrict__ C, const float* __restrict__ bias,
              int Kp, int Nreal)
{
    extern __shared__ __align__(16) char smem[];
    __nv_bfloat16* pAh = (__nv_bfloat16*)smem;
    uint32_t sAh = smem_u32g(pAh);
    uint32_t sAl = sAh + 2 * TBYT;
    uint32_t sBh = sAh + 4 * TBYT;
    uint32_t sBl = sAh + 6 * TBYT;

    int tid  = threadIdx.x;
    int lane = tid & 31, wid = tid >> 5;
    int wm = wid & 1;              // 0..1 : m offset wm*64
    int wn = wid >> 1;             // 0..3 : n offset wn*32
    int bm = blockIdx.y * 128;
    int bn = blockIdx.x * 128;
    int r  = lane >> 2;
    int q2 = (lane & 3) * 2;

    // per-lane ldmatrix row/col components
    int aRow = lane & 15;
    int aCol = (lane >> 4) << 3;
    int bRow = (lane & 7) + ((lane & 16) >> 1);
    int bCol = lane & 8;

    float acc[4][4][4];
#pragma unroll
    for (int mt = 0; mt < 4; mt++)
#pragma unroll
        for (int nt = 0; nt < 4; nt++)
#pragma unroll
            for (int j = 0; j < 4; j++) acc[mt][nt][j] = 0.f;

    const int nch = Kp >> 5;

    auto issue = [&](int ch) {
        int k0 = ch << 5;
        uint32_t stoff = (uint32_t)(ch & 1) * TBYT;
#pragma unroll
        for (int t = 0; t < 2; t++) {
            int idx = tid + t * 256;
            int row = idx >> 2, seg = (idx & 3) * 8;
            uint32_t doff = stoff + (uint32_t)(row * APAD + seg) * 2;
            size_t aoff = (size_t)(bm + row) * Kp + k0 + seg;
            size_t boff = (size_t)(bn + row) * Kp + k0 + seg;
            cpa16(sAh + doff, Ah + aoff);
            cpa16(sAl + doff, Al + aoff);
            cpa16(sBh + doff, Bh + boff);
            cpa16(sBl + doff, Bl + boff);
        }
        asm volatile("cp.async.commit_group;" ::: "memory");
    };

    issue(0);
    for (int ch = 0; ch < nch; ch++) {
        if (ch + 1 < nch) {
            issue(ch + 1);
            asm volatile("cp.async.wait_group 1;" ::: "memory");
        } else {
            asm volatile("cp.async.wait_group 0;" ::: "memory");
        }
        __syncthreads();

        uint32_t stoff = (uint32_t)(ch & 1) * TBYT;
#pragma unroll
        for (int ks = 0; ks < 32; ks += 16) {
            uint32_t bh[4][2], bl[4][2];
#pragma unroll
            for (int p = 0; p < 2; p++) {
                uint32_t off = stoff +
                    (uint32_t)(((wn * 32 + p * 16 + bRow) * APAD) + ks + bCol) * 2;
                uint32_t r4[4];
                ldsm4(r4, sBh + off);
                bh[2*p][0] = r4[0]; bh[2*p][1] = r4[1];
                bh[2*p+1][0] = r4[2]; bh[2*p+1][1] = r4[3];
                ldsm4(r4, sBl + off);
                bl[2*p][0] = r4[0]; bl[2*p][1] = r4[1];
                bl[2*p+1][0] = r4[2]; bl[2*p+1][1] = r4[3];
            }
#pragma unroll
            for (int mt = 0; mt < 4; mt++) {
                uint32_t off = stoff +
                    (uint32_t)(((wm * 64 + mt * 16 + aRow) * APAD) + ks + aCol) * 2;
                uint32_t ah[4], al[4];
                ldsm4(ah, sAh + off);
                ldsm4(al, sAl + off);
#pragma unroll
                for (int nt = 0; nt < 4; nt++) {
                    MMA_BF16(acc[mt][nt], ah, bh[nt]);
                    MMA_BF16(acc[mt][nt], ah, bl[nt]);
                    MMA_BF16(acc[mt][nt], al, bh[nt]);
                }
            }
        }
        __syncthreads();
    }

    // ---- epilogue ----
#pragma unroll
    for (int mt = 0; mt < 4; mt++) {
        int row0 = bm + wm * 64 + mt * 16 + r;
        int row1 = row0 + 8;
#pragma unroll
        for (int nt = 0; nt < 4; nt++) {
            int col = bn + wn * 32 + nt * 8 + q2;
            if (col >= Nreal) continue;
            float2 v0 = make_float2(acc[mt][nt][0], acc[mt][nt][1]);
            float2 v1 = make_float2(acc[mt][nt][2], acc[mt][nt][3]);
            if (EPI == 1) {
                float2 bb = *(const float2*)(bias + col);
                v0.x += bb.x; v0.y += bb.y;
                v1.x += bb.x; v1.y += bb.y;
            }
            if (row0 < NN) *(float2*)(C + (size_t)row0 * Nreal + col) = v0;
            if (row1 < NN) *(float2*)(C + (size_t)row1 * Nreal + col) = v1;
        }
    }
}

// ---------------------------------------------------------------------------
// Pull aggregation, one block (128 thr) per node.
// PASS==1: in=g_H1 ; out r1 = relu(self+Σ+b1)
// PASS==2: in=g_r1 ; out a2h/a2l = bf16 hi/lo split of (self+Σ)
// ---------------------------------------------------------------------------
template<int PASS>
__global__ __launch_bounds__(128)
void k_pull(const float* __restrict__ b1)
{
    int n = blockIdx.x;
    int q = threadIdx.x;
    bool act = q < (H1D / 4);

    const float* In = (PASS == 1) ? g_H1 : g_r1;
    float din = g_dinv[n];
    float s2  = din * din;

    float4 acc = make_float4(0.f, 0.f, 0.f, 0.f);
    if (act) {
        float4 v = *((const float4*)(In + (size_t)n * H1D) + q);
        acc = make_float4(v.x * s2, v.y * s2, v.z * s2, v.w * s2);
    }

    int beg = g_off[n], end = g_off[n + 1];
#pragma unroll 2
    for (int j = beg; j < end; j++) {
        int   s  = g_csrc[j];
        float nm = g_cnorm[j];
        if (act) {
            float4 v = *((const float4*)(In + (size_t)s * H1D) + q);
            acc.x += v.x * nm; acc.y += v.y * nm;
            acc.z += v.z * nm; acc.w += v.w * nm;
        }
    }

    if (!act) return;
    if (PASS == 1) {
        float4 bb = *((const float4*)b1 + q);
        acc.x = fmaxf(acc.x + bb.x, 0.f);
        acc.y = fmaxf(acc.y + bb.y, 0.f);
        acc.z = fmaxf(acc.z + bb.z, 0.f);
        acc.w = fmaxf(acc.w + bb.w, 0.f);
        *((float4*)(g_r1 + (size_t)n * H1D) + q) = acc;
    } else {
        __nv_bfloat16 h0 = __float2bfloat16(acc.x);
        __nv_bfloat16 h1 = __float2bfloat16(acc.y);
        __nv_bfloat16 h2 = __float2bfloat16(acc.z);
        __nv_bfloat16 h3 = __float2bfloat16(acc.w);
        __nv_bfloat162 H0, H1v, L0, L1;
        H0.x = h0; H0.y = h1; H1v.x = h2; H1v.y = h3;
        L0.x = __float2bfloat16(acc.x - __bfloat162float(h0));
        L0.y = __float2bfloat16(acc.y - __bfloat162float(h1));
        L1.x = __float2bfloat16(acc.z - __bfloat162float(h2));
        L1.y = __float2bfloat16(acc.w - __bfloat162float(h3));
        size_t o = (size_t)n * K2P + q * 4;
        *(__nv_bfloat162*)(g_a2h + o)     = H0;
        *(__nv_bfloat162*)(g_a2h + o + 2) = H1v;
        *(__nv_bfloat162*)(g_a2l + o)     = L0;
        *(__nv_bfloat162*)(g_a2l + o + 2) = L1;
    }
}

// ---------------------------------------------------------------------------
extern "C" void kernel_launch(void* const* d_in, const int* in_sizes, int n_in,
                              void* d_out, int out_size)
{
    const float* x  = (const float*)d_in[0];
    const void*  ei = d_in[1];
    const float* W1 = (const float*)d_in[2];
    const float* b1 = (const float*)d_in[3];
    const float* W2 = (const float*)d_in[4];
    const float* b2 = (const float*)d_in[5];
    float* out = (float*)d_out;

    int E = in_sizes[1] / 2;

    float *pH1;
    cudaGetSymbolAddress((void**)&pH1, g_H1);
    __nv_bfloat16 *pxh, *pxl, *pa2h, *pa2l, *pw1h, *pw1l, *pw2h, *pw2l;
    cudaGetSymbolAddress((void**)&pxh,  g_xh);
    cudaGetSymbolAddress((void**)&pxl,  g_xl);
    cudaGetSymbolAddress((void**)&pa2h, g_a2h);
    cudaGetSymbolAddress((void**)&pa2l, g_a2l);
    cudaGetSymbolAddress((void**)&pw1h, g_w1h);
    cudaGetSymbolAddress((void**)&pw1l, g_w1l);
    cudaGetSymbolAddress((void**)&pw2h, g_w2h);
    cudaGetSymbolAddress((void**)&pw2l, g_w2l);

    cudaFuncSetAttribute(mma_gemm<0>, cudaFuncAttributeMaxDynamicSharedMemorySize, GSMEM);
    cudaFuncSetAttribute(mma_gemm<1>, cudaFuncAttributeMaxDynamicSharedMemorySize, GSMEM);

    // 0) init + dtype probe
    k_init<<<(NN + 255) / 256, 256>>>();
    k_detectP<<<8, 256>>>((const int*)ei, in_sizes[1]);

    // 1) degrees, dinv, CSR
    k_count<<<(E + 255) / 256, 256>>>(ei, E);
    k_dinv<<<(NN + 255) / 256, 256>>>();
    k_scan<<<1, 1024>>>();
    k_place<<<(E + 255) / 256, 256>>>(ei, E);

    // 2) splits for GEMM inputs
    {
        long long tot = (long long)MPAD * (K1P / 2);
        k_splitA<<<(int)((tot + 255) / 256), 256>>>(x, pxh, pxl, NN, INCH, K1P);
        k_splitB<<<(N1P * K1P + 255) / 256, 256>>>(W1, pw1h, pw1l, INCH, H1D, K1P, N1P);
        k_splitB<<<(N2P * K2P + 255) / 256, 256>>>(W2, pw2h, pw2l, H1D, H2D, K2P, N2P);
    }

    // 3) H1 = x @ W1
    mma_gemm<0><<<dim3(N1P / 128, MPAD / 128), 256, GSMEM>>>(
        pxh, pxl, pw1h, pw1l, pH1, nullptr, K1P, H1D);

    // 4) pull-aggregate layer 1 + relu + bias  -> r1
    k_pull<1><<<NN, 128>>>(b1);

    // 5) pull-aggregate layer 2 + bf16 split   -> a2h/a2l
    k_pull<2><<<NN, 128>>>(nullptr);

    // 6) out = agg2 @ W2 + b2
    mma_gemm<1><<<dim3(N2P / 128, MPAD / 128), 256, GSMEM>>>(
        pa2h, pa2l, pw2h, pw2l, out, b2, K2P, H2D);
}

// round 16
// speedup vs baseline: 2.1679x; 1.0114x over previous
#include <cuda_runtime.h>
#include <cuda_bf16.h>
#include <cstdint>
#include <cstddef>

#define NN   50000
#define MPAD 50176          // 196 * 256
#define INCH 512
#define H1D  400
#define H2D  800
#define K1P  512
#define K2P  448
#define N1P  512
#define N2P  896
#define EMAX 1700000

// ---------------- fp32 scratch ----------------
__device__ float g_H1  [(size_t)NN * H1D];   // H1 * dinv[row]  (prescaled)
__device__ float g_r1  [(size_t)NN * H1D];   // relu(...) * dinv[row] (prescaled)
__device__ float g_dinv[NN];
__device__ int   g_deg [NN];
__device__ int   g_off [NN + 1];
__device__ int   g_cur [NN];
__device__ int   g_csrc[EMAX];
__device__ int   g_is64;

// ---------------- bf16 split scratch (zero-padded; pads never written) ------
__device__ __nv_bfloat16 g_xh [(size_t)MPAD * K1P];
__device__ __nv_bfloat16 g_xl [(size_t)MPAD * K1P];
__device__ __nv_bfloat16 g_a2h[(size_t)MPAD * K2P];
__device__ __nv_bfloat16 g_a2l[(size_t)MPAD * K2P];
__device__ __nv_bfloat16 g_w1h[(size_t)N1P * K1P];
__device__ __nv_bfloat16 g_w1l[(size_t)N1P * K1P];
__device__ __nv_bfloat16 g_w2h[(size_t)N2P * K2P];
__device__ __nv_bfloat16 g_w2l[(size_t)N2P * K2P];

// ---------------------------------------------------------------------------
__global__ void k_init() {
    int i = blockIdx.x * blockDim.x + threadIdx.x;
    if (i < NN) g_deg[i] = 0;
    if (i == 0) g_is64 = 1;
}
__global__ void k_detectP(const int* __restrict__ w, int nwords) {
    int i = (blockIdx.x * blockDim.x + threadIdx.x) * 2 + 1;
    int lim = nwords < 4096 ? nwords : 4096;
    if (i < lim && w[i] != 0) g_is64 = 0;
}
__device__ __forceinline__ int edge_at(const void* ei, long long idx) {
    if (g_is64) return (int)((const long long*)ei)[idx];
    return ((const int*)ei)[idx];
}

__global__ void k_count(const void* __restrict__ ei, int E) {
    int e = blockIdx.x * blockDim.x + threadIdx.x;
    if (e >= E) return;
    int d = edge_at(ei, (long long)E + e);
    if ((unsigned)d < NN) atomicAdd(&g_deg[d], 1);
}

// ---------------------------------------------------------------------------
// Exclusive scan (warp shuffles) + dinv fused.
// ---------------------------------------------------------------------------
__global__ __launch_bounds__(1024)
void k_scan() {
    __shared__ int wsum[32];
    __shared__ int carry;
    int tid = threadIdx.x, lane = tid & 31, wid = tid >> 5;
    if (tid == 0) carry = 0;
    __syncthreads();
    for (int base = 0; base < NN; base += 1024) {
        int i = base + tid;
        int v = (i < NN) ? g_deg[i] : 0;
        int incl = v;
#pragma unroll
        for (int off = 1; off < 32; off <<= 1) {
            int t = __shfl_up_sync(0xffffffffu, incl, off);
            if (lane >= off) incl += t;
        }
        if (lane == 31) wsum[wid] = incl;
        __syncthreads();
        if (wid == 0) {
            int s = wsum[lane];
#pragma unroll
            for (int off = 1; off < 32; off <<= 1) {
                int t = __shfl_up_sync(0xffffffffu, s, off);
                if (lane >= off) s += t;
            }
            wsum[lane] = s;
        }
        __syncthreads();
        int wpre = (wid == 0) ? 0 : wsum[wid - 1];
        int excl = carry + wpre + incl - v;
        if (i < NN) {
            g_off[i] = excl;
            g_cur[i] = excl;
            g_dinv[i] = rsqrtf((float)v + 1.0f);
        }
        __syncthreads();
        if (tid == 0) carry += wsum[31];
        __syncthreads();
    }
    if (threadIdx.x == 0) g_off[NN] = carry;
}

__global__ void k_place(const void* __restrict__ ei, int E) {
    int e = blockIdx.x * blockDim.x + threadIdx.x;
    if (e >= E) return;
    int s = edge_at(ei, e);
    int d = edge_at(ei, (long long)E + e);
    if ((unsigned)s >= NN || (unsigned)d >= NN) return;
    int pos = atomicAdd(&g_cur[d], 1);
    if (pos < EMAX) g_csrc[pos] = s;
}

// ---------------------------------------------------------------------------
// fp32 -> bf16 hi/lo splits
// ---------------------------------------------------------------------------
__global__ void k_splitA(const float* __restrict__ src,
                         __nv_bfloat16* __restrict__ dh,
                         __nv_bfloat16* __restrict__ dl,
                         int M, int Ks, int Kp)
{
    long long tot = (long long)MPAD * (Kp >> 1);
    long long i2 = (long long)blockIdx.x * blockDim.x + threadIdx.x;
    if (i2 >= tot) return;
    int r  = (int)(i2 / (Kp >> 1));
    int c2 = (int)(i2 - (long long)r * (Kp >> 1)) * 2;
    float v0 = 0.f, v1 = 0.f;
    if (r < M) {
        if (c2     < Ks) v0 = src[(size_t)r * Ks + c2];
        if (c2 + 1 < Ks) v1 = src[(size_t)r * Ks + c2 + 1];
    }
    __nv_bfloat16 h0 = __float2bfloat16(v0), h1 = __float2bfloat16(v1);
    __nv_bfloat162 H, L;
    H.x = h0; H.y = h1;
    L.x = __float2bfloat16(v0 - __bfloat162float(h0));
    L.y = __float2bfloat16(v1 - __bfloat162float(h1));
    *(__nv_bfloat162*)(dh + (size_t)r * Kp + c2) = H;
    *(__nv_bfloat162*)(dl + (size_t)r * Kp + c2) = L;
}

__global__ void k_splitB(const float* __restrict__ W,
                         __nv_bfloat16* __restrict__ dh,
                         __nv_bfloat16* __restrict__ dl,
                         int K, int N, int Kp, int Np)
{
    int idx = blockIdx.x * blockDim.x + threadIdx.x;
    if (idx >= Np * Kp) return;
    int n = idx / Kp, k = idx - n * Kp;
    float v = (n < N && k < K) ? W[(size_t)k * N + n] : 0.f;
    __nv_bfloat16 h = __float2bfloat16(v);
    dh[idx] = h;
    dl[idx] = __float2bfloat16(v - __bfloat162float(h));
}

// ---------------------------------------------------------------------------
// Split-bf16 GEMM, 3-stage cp.async + ldmatrix.
// CTA tile 256x128, BK=32, 16 warps (4m x 4n), warp tile 64x32, 512 threads.
// acc += Ah*Bh + Ah*Bl + Al*Bh
// EPI==0: C = acc * dinv[row]  ;  EPI==1: C = acc + bias[col]
// ---------------------------------------------------------------------------
#define MMA_BF16(c, a, b) \
    asm volatile("mma.sync.aligned.m16n8k16.row.col.f32.bf16.bf16.f32 " \
        "{%0,%1,%2,%3}, {%4,%5,%6,%7}, {%8,%9}, {%0,%1,%2,%3};" \
        : "+f"((c)[0]), "+f"((c)[1]), "+f"((c)[2]), "+f"((c)[3]) \
        : "r"((a)[0]), "r"((a)[1]), "r"((a)[2]), "r"((a)[3]), \
          "r"((b)[0]), "r"((b)[1]))

#define APAD   40                    // row stride 80B -> conflict-free ldmatrix
#define OFF_AH 0
#define OFF_AL (256 * APAD * 2)      // 20480
#define OFF_BH (2 * 256 * APAD * 2)  // 40960
#define OFF_BL (OFF_BH + 128 * APAD * 2)
#define STAGEB (OFF_BL + 128 * APAD * 2)   // 61440 bytes per stage
#define NSTAGE 3
#define GSMEM  (NSTAGE * STAGEB)

__device__ __forceinline__ uint32_t smem_u32g(const void* p) {
    uint32_t a;
    asm("{ .reg .u64 t; cvta.to.shared.u64 t, %1; cvt.u32.u64 %0, t; }"
        : "=r"(a) : "l"(p));
    return a;
}
__device__ __forceinline__ void cpa16(uint32_t dst, const void* src) {
    asm volatile("cp.async.cg.shared.global [%0], [%1], 16;"
                 :: "r"(dst), "l"(src) : "memory");
}
__device__ __forceinline__ void ldsm4(uint32_t* r, uint32_t addr) {
    asm volatile("ldmatrix.sync.aligned.m8n8.x4.shared.b16 {%0,%1,%2,%3}, [%4];"
                 : "=r"(r[0]), "=r"(r[1]), "=r"(r[2]), "=r"(r[3]) : "r"(addr));
}

template<int EPI>
__global__ __launch_bounds__(512)
void mma_gemm(const __nv_bfloat16* __restrict__ Ah, const __nv_bfloat16* __restrict__ Al,
              const __nv_bfloat16* __restrict__ Bh, const __nv_bfloat16* __restrict__ Bl,
              float* __restrict__ C, const float* __restrict__ bias,
              int Kp, int Nreal)
{
    extern __shared__ __align__(16) char smem[];
    uint32_t sbase = smem_u32g(smem);

    int tid  = threadIdx.x;
    int lane = tid & 31, wid = tid >> 5;
    int wm = wid & 3;              // m offset wm*64
    int wn = wid >> 2;             // n offset wn*32
    int bm = blockIdx.y * 256;
    int bn = blockIdx.x * 128;
    int r  = lane >> 2;
    int q2 = (lane & 3) * 2;

    int aRow = lane & 15;
    int aCol = (lane >> 4) << 3;
    int bRow = (lane & 7) + ((lane & 16) >> 1);
    int bCol = lane & 8;

    float acc[4][4][4];
#pragma unroll
    for (int mt = 0; mt < 4; mt++)
#pragma unroll
        for (int nt = 0; nt < 4; nt++)
#pragma unroll
            for (int j = 0; j < 4; j++) acc[mt][nt][j] = 0.f;

    const int nch = Kp >> 5;

    auto issue = [&](int ch) {
        int k0 = ch << 5;
        uint32_t st = sbase + (uint32_t)(ch % NSTAGE) * STAGEB;
        // A: 256 rows x 32 k, hi+lo : 2 x (1024 cp) ; B: 128 rows : 2 x (512 cp)
#pragma unroll
        for (int t = 0; t < 2; t++) {
            int idx = tid + t * 512;
            int row = idx >> 2, seg = (idx & 3) * 8;
            uint32_t doff = (uint32_t)(row * APAD + seg) * 2;
            size_t aoff = (size_t)(bm + row) * Kp + k0 + seg;
            cpa16(st + OFF_AH + doff, Ah + aoff);
            cpa16(st + OFF_AL + doff, Al + aoff);
        }
        {
            int row = tid >> 2, seg = (tid & 3) * 8;
            uint32_t doff = (uint32_t)(row * APAD + seg) * 2;
            size_t boff = (size_t)(bn + row) * Kp + k0 + seg;
            cpa16(st + OFF_BH + doff, Bh + boff);
            cpa16(st + OFF_BL + doff, Bl + boff);
        }
        asm volatile("cp.async.commit_group;" ::: "memory");
    };

    issue(0);
    issue(1);
    for (int ch = 0; ch < nch; ch++) {
        if (ch + 2 < nch) {
            issue(ch + 2);
            asm volatile("cp.async.wait_group 2;" ::: "memory");
        } else if (ch + 1 < nch) {
            asm volatile("cp.async.wait_group 1;" ::: "memory");
        } else {
            asm volatile("cp.async.wait_group 0;" ::: "memory");
        }
        __syncthreads();

        uint32_t st = sbase + (uint32_t)(ch % NSTAGE) * STAGEB;
#pragma unroll
        for (int ks = 0; ks < 32; ks += 16) {
            uint32_t bh[4][2], bl[4][2];
#pragma unroll
            for (int p = 0; p < 2; p++) {
                uint32_t off = (uint32_t)(((wn * 32 + p * 16 + bRow) * APAD) + ks + bCol) * 2;
                uint32_t r4[4];
                ldsm4(r4, st + OFF_BH + off);
                bh[2*p][0] = r4[0]; bh[2*p][1] = r4[1];
                bh[2*p+1][0] = r4[2]; bh[2*p+1][1] = r4[3];
                ldsm4(r4, st + OFF_BL + off);
                bl[2*p][0] = r4[0]; bl[2*p][1] = r4[1];
                bl[2*p+1][0] = r4[2]; bl[2*p+1][1] = r4[3];
            }
#pragma unroll
            for (int mt = 0; mt < 4; mt++) {
                uint32_t off = (uint32_t)(((wm * 64 + mt * 16 + aRow) * APAD) + ks + aCol) * 2;
                uint32_t ah[4], al[4];
                ldsm4(ah, st + OFF_AH + off);
                ldsm4(al, st + OFF_AL + off);
#pragma unroll
                for (int nt = 0; nt < 4; nt++) {
                    MMA_BF16(acc[mt][nt], ah, bh[nt]);
                    MMA_BF16(acc[mt][nt], ah, bl[nt]);
                    MMA_BF16(acc[mt][nt], al, bh[nt]);
                }
            }
        }
        __syncthreads();
    }

    // ---- epilogue ----
#pragma unroll
    for (int mt = 0; mt < 4; mt++) {
        int row0 = bm + wm * 64 + mt * 16 + r;
        int row1 = row0 + 8;
        float s0 = 1.f, s1 = 1.f;
        if (EPI == 0) {
            if (row0 < NN) s0 = g_dinv[row0];
            if (row1 < NN) s1 = g_dinv[row1];
        }
#pragma unroll
        for (int nt = 0; nt < 4; nt++) {
            int col = bn + wn * 32 + nt * 8 + q2;
            if (col >= Nreal) continue;
            float2 v0 = make_float2(acc[mt][nt][0], acc[mt][nt][1]);
            float2 v1 = make_float2(acc[mt][nt][2], acc[mt][nt][3]);
            if (EPI == 0) {
                v0.x *= s0; v0.y *= s0;
                v1.x *= s1; v1.y *= s1;
            } else {
                float2 bb = *(const float2*)(bias + col);
                v0.x += bb.x; v0.y += bb.y;
                v1.x += bb.x; v1.y += bb.y;
            }
            if (row0 < NN) *(float2*)(C + (size_t)row0 * Nreal + col) = v0;
            if (row1 < NN) *(float2*)(C + (size_t)row1 * Nreal + col) = v1;
        }
    }
}

// ---------------------------------------------------------------------------
// Pull aggregation (unweighted sums of prescaled rows), one 128-thr block/node.
// PASS==1: in=g_H1 (prescaled) ; r1p = relu(dinv*acc + b1) * dinv
// PASS==2: in=g_r1 (prescaled) ; a2h/a2l = bf16 split of dinv*acc
// ---------------------------------------------------------------------------
template<int PASS>
__global__ __launch_bounds__(128)
void k_pull(const float* __restrict__ b1)
{
    int n = blockIdx.x;
    int q = threadIdx.x;
    bool act = q < (H1D / 4);

    const float* In = (PASS == 1) ? g_H1 : g_r1;
    float din = g_dinv[n];

    float4 acc = make_float4(0.f, 0.f, 0.f, 0.f);
    if (act) acc = *((const float4*)(In + (size_t)n * H1D) + q);   // self (prescaled)

    int beg = g_off[n], end = g_off[n + 1];
#pragma unroll 2
    for (int j = beg; j < end; j++) {
        int s = g_csrc[j];
        if (act) {
            float4 v = *((const float4*)(In + (size_t)s * H1D) + q);
            acc.x += v.x; acc.y += v.y; acc.z += v.z; acc.w += v.w;
        }
    }

    if (!act) return;
    if (PASS == 1) {
        float4 bb = *((const float4*)b1 + q);
        acc.x = fmaxf(acc.x * din + bb.x, 0.f) * din;
        acc.y = fmaxf(acc.y * din + bb.y, 0.f) * din;
        acc.z = fmaxf(acc.z * din + bb.z, 0.f) * din;
        acc.w = fmaxf(acc.w * din + bb.w, 0.f) * din;
        *((float4*)(g_r1 + (size_t)n * H1D) + q) = acc;
    } else {
        acc.x *= din; acc.y *= din; acc.z *= din; acc.w *= din;
        __nv_bfloat16 h0 = __float2bfloat16(acc.x);
        __nv_bfloat16 h1 = __float2bfloat16(acc.y);
        __nv_bfloat16 h2 = __float2bfloat16(acc.z);
        __nv_bfloat16 h3 = __float2bfloat16(acc.w);
        __nv_bfloat162 H0, H1v, L0, L1;
        H0.x = h0; H0.y = h1; H1v.x = h2; H1v.y = h3;
        L0.x = __float2bfloat16(acc.x - __bfloat162float(h0));
        L0.y = __float2bfloat16(acc.y - __bfloat162float(h1));
        L1.x = __float2bfloat16(acc.z - __bfloat162float(h2));
        L1.y = __float2bfloat16(acc.w - __bfloat162float(h3));
        size_t o = (size_t)n * K2P + q * 4;
        *(__nv_bfloat162*)(g_a2h + o)     = H0;
        *(__nv_bfloat162*)(g_a2h + o + 2) = H1v;
        *(__nv_bfloat162*)(g_a2l + o)     = L0;
        *(__nv_bfloat162*)(g_a2l + o + 2) = L1;
    }
}

// ---------------------------------------------------------------------------
extern "C" void kernel_launch(void* const* d_in, const int* in_sizes, int n_in,
                              void* d_out, int out_size)
{
    const float* x  = (const float*)d_in[0];
    const void*  ei = d_in[1];
    const float* W1 = (const float*)d_in[2];
    const float* b1 = (const float*)d_in[3];
    const float* W2 = (const float*)d_in[4];
    const float* b2 = (const float*)d_in[5];
    float* out = (float*)d_out;

    int E = in_sizes[1] / 2;

    float *pH1;
    cudaGetSymbolAddress((void**)&pH1, g_H1);
    __nv_bfloat16 *pxh, *pxl, *pa2h, *pa2l, *pw1h, *pw1l, *pw2h, *pw2l;
    cudaGetSymbolAddress((void**)&pxh,  g_xh);
    cudaGetSymbolAddress((void**)&pxl,  g_xl);
    cudaGetSymbolAddress((void**)&pa2h, g_a2h);
    cudaGetSymbolAddress((void**)&pa2l, g_a2l);
    cudaGetSymbolAddress((void**)&pw1h, g_w1h);
    cudaGetSymbolAddress((void**)&pw1l, g_w1l);
    cudaGetSymbolAddress((void**)&pw2h, g_w2h);
    cudaGetSymbolAddress((void**)&pw2l, g_w2l);

    cudaFuncSetAttribute(mma_gemm<0>, cudaFuncAttributeMaxDynamicSharedMemorySize, GSMEM);
    cudaFuncSetAttribute(mma_gemm<1>, cudaFuncAttributeMaxDynamicSharedMemorySize, GSMEM);

    // 0) init + dtype probe
    k_init<<<(NN + 255) / 256, 256>>>();
    k_detectP<<<8, 256>>>((const int*)ei, in_sizes[1]);

    // 1) degrees, scan(+dinv), CSR placement
    k_count<<<(E + 255) / 256, 256>>>(ei, E);
    k_scan<<<1, 1024>>>();
    k_place<<<(E + 255) / 256, 256>>>(ei, E);

    // 2) splits for GEMM inputs
    {
        long long tot = (long long)MPAD * (K1P / 2);
        k_splitA<<<(int)((tot + 255) / 256), 256>>>(x, pxh, pxl, NN, INCH, K1P);
        k_splitB<<<(N1P * K1P + 255) / 256, 256>>>(W1, pw1h, pw1l, INCH, H1D, K1P, N1P);
        k_splitB<<<(N2P * K2P + 255) / 256, 256>>>(W2, pw2h, pw2l, H1D, H2D, K2P, N2P);
    }

    // 3) H1' = (x @ W1) * dinv[row]
    mma_gemm<0><<<dim3(N1P / 128, MPAD / 256), 512, GSMEM>>>(
        pxh, pxl, pw1h, pw1l, pH1, nullptr, K1P, H1D);

    // 4) pull 1: r1' = relu(dinv*Σ + b1) * dinv
    k_pull<1><<<NN, 128>>>(b1);

    // 5) pull 2: agg2 = dinv*Σ -> bf16 split
    k_pull<2><<<NN, 128>>>(nullptr);

    // 6) out = agg2 @ W2 + b2
    mma_gemm<1><<<dim3(N2P / 128, MPAD / 256), 512, GSMEM>>>(
        pa2h, pa2l, pw2h, pw2l, out, b2, K2P, H2D);
}